// round 2
// baseline (speedup 1.0000x reference)
#include <cuda_runtime.h>
#include <cuda_bf16.h>
#include <math.h>

// Problem constants (fixed shapes for this problem)
#define B 32
#define S 2048
#define H 1024
#define M_TOTAL (B * S)        // 65536 rows of the big GEMM

// ---------------------------------------------------------------------------
// Scratch (no allocations allowed -> __device__ globals)
// ---------------------------------------------------------------------------
__device__ float g_qp[B * H];            // q_proj + Wa_b + Ua_b  (128 KB)
__device__ float g_spart[8 * M_TOTAL];   // per-n-tile partial scores (2 MB)
__device__ float g_cpart[4 * B * H];     // per-s-chunk partial context (512 KB)

// ---------------------------------------------------------------------------
// Packed f32x2 helpers (Blackwell packed fp32 pipe: 2x FFMA throughput)
// ---------------------------------------------------------------------------
__device__ __forceinline__ unsigned long long pk2(float x, float y) {
    unsigned long long r;
    asm("mov.b64 %0, {%1, %2};" : "=l"(r)
        : "r"(__float_as_uint(x)), "r"(__float_as_uint(y)));
    return r;
}
__device__ __forceinline__ float2 upk2(unsigned long long v) {
    unsigned int a, b;
    asm("mov.b64 {%0, %1}, %2;" : "=r"(a), "=r"(b) : "l"(v));
    return make_float2(__uint_as_float(a), __uint_as_float(b));
}
#define FMA2(acc, a2, b2) \
    asm("fma.rn.f32x2 %0, %1, %2, %0;" : "+l"(acc) : "l"(a2), "l"(b2))

// ---------------------------------------------------------------------------
// K1: q_proj[b][o] = query[b,:] . Wa_w[o,:] + Wa_b[o] + Ua_b[o]
// One warp per (b,o). 32768 warps.
// ---------------------------------------------------------------------------
__global__ void k1_qproj(const float* __restrict__ query,
                         const float* __restrict__ Wa_w,
                         const float* __restrict__ Wa_b,
                         const float* __restrict__ Ua_b) {
    int gw   = (blockIdx.x * blockDim.x + threadIdx.x) >> 5;
    int lane = threadIdx.x & 31;
    int b = gw >> 10;
    int o = gw & 1023;
    const float* qr = query + b * H;
    const float* wr = Wa_w + (size_t)o * H;
    float acc = 0.f;
#pragma unroll 4
    for (int i = lane; i < H; i += 32)
        acc += qr[i] * wr[i];
#pragma unroll
    for (int off = 16; off; off >>= 1)
        acc += __shfl_xor_sync(0xFFFFFFFFu, acc, off);
    if (lane == 0)
        g_qp[gw] = acc + Wa_b[o] + Ua_b[o];
}

// ---------------------------------------------------------------------------
// K2: fused  scores_part[nt][row] = sum_{col in n-tile} Va[col] *
//            tanh( keys[row,:] . Ua_w[col,:]  + g_qp[b][col] )
// 128x128x8 register-blocked SGEMM, f32x2 inner loop, fused tanh epilogue.
// grid = (8 n-tiles, 512 m-tiles), 256 threads.
// ---------------------------------------------------------------------------
__global__ __launch_bounds__(256, 2)
void k2_gemm_tanh(const float* __restrict__ keys,
                  const float* __restrict__ Ua_w,
                  const float* __restrict__ Va_w) {
    __shared__ float sA[8 * 132];
    __shared__ float sB[8 * 132];
    __shared__ float red[128 * 16];

    const int tid = threadIdx.x;
    const int tx = tid & 15;
    const int ty = tid >> 4;
    const int n0 = blockIdx.x * 128;
    const int m0 = blockIdx.y * 128;
    const int b  = blockIdx.y >> 4;          // S/128 = 16 m-tiles per batch

    // cooperative tile load indexing: 256 threads load 128x8 floats (as float4)
    const int lrow = tid >> 1;               // 0..127
    const int lcol = (tid & 1) * 4;          // 0 or 4
    const float* Ag = keys + (size_t)(m0 + lrow) * H + lcol;
    const float* Bg = Ua_w + (size_t)(n0 + lrow) * H + lcol;

    float4 av = *(const float4*)Ag;
    float4 bv = *(const float4*)Bg;

    unsigned long long acc[4][8];
#pragma unroll
    for (int i = 0; i < 4; ++i)
#pragma unroll
        for (int j = 0; j < 8; ++j) acc[i][j] = 0ull;

    const int KT = H / 8;                    // 128 k-tiles
    for (int kt = 0; kt < KT; ++kt) {
        // store current tile (transposed: s[k][m])
        sA[(lcol + 0) * 132 + lrow] = av.x;
        sA[(lcol + 1) * 132 + lrow] = av.y;
        sA[(lcol + 2) * 132 + lrow] = av.z;
        sA[(lcol + 3) * 132 + lrow] = av.w;
        sB[(lcol + 0) * 132 + lrow] = bv.x;
        sB[(lcol + 1) * 132 + lrow] = bv.y;
        sB[(lcol + 2) * 132 + lrow] = bv.z;
        sB[(lcol + 3) * 132 + lrow] = bv.w;
        __syncthreads();

        // prefetch next tile into registers (hides HBM/L2 latency under compute)
        float4 av2 = av, bv2 = bv;
        if (kt + 1 < KT) {
            av2 = *(const float4*)(Ag + (size_t)(kt + 1) * 8);
            bv2 = *(const float4*)(Bg + (size_t)(kt + 1) * 8);
        }

#pragma unroll
        for (int k = 0; k < 8; ++k) {
            float4 a0 = *(const float4*)&sA[k * 132 + 4 * ty];
            float4 a1 = *(const float4*)&sA[k * 132 + 64 + 4 * ty];
            float4 b0 = *(const float4*)&sB[k * 132 + 4 * tx];
            float4 b1 = *(const float4*)&sB[k * 132 + 64 + 4 * tx];

            unsigned long long a2[4];
            a2[0] = pk2(a0.x, a0.y);
            a2[1] = pk2(a0.z, a0.w);
            a2[2] = pk2(a1.x, a1.y);
            a2[3] = pk2(a1.z, a1.w);
            unsigned long long bb[8];
            bb[0] = pk2(b0.x, b0.x); bb[1] = pk2(b0.y, b0.y);
            bb[2] = pk2(b0.z, b0.z); bb[3] = pk2(b0.w, b0.w);
            bb[4] = pk2(b1.x, b1.x); bb[5] = pk2(b1.y, b1.y);
            bb[6] = pk2(b1.z, b1.z); bb[7] = pk2(b1.w, b1.w);

#pragma unroll
            for (int rp = 0; rp < 4; ++rp)
#pragma unroll
                for (int c = 0; c < 8; ++c)
                    FMA2(acc[rp][c], a2[rp], bb[c]);
        }
        __syncthreads();
        av = av2;
        bv = bv2;
    }

    // ---------------- fused epilogue: tanh + Va dot ----------------
    float va[8], qp[8];
#pragma unroll
    for (int j = 0; j < 8; ++j) {
        int col = n0 + ((j < 4) ? (4 * tx + j) : (64 + 4 * tx + (j - 4)));
        va[j] = Va_w[col];
        qp[j] = g_qp[b * H + col];
    }

    float part[8];
#pragma unroll
    for (int i = 0; i < 8; ++i) part[i] = 0.f;

#pragma unroll
    for (int rp = 0; rp < 4; ++rp) {
#pragma unroll
        for (int c = 0; c < 8; ++c) {
            float2 v = upk2(acc[rp][c]);
            part[rp * 2 + 0] += va[c] * tanhf(v.x + qp[c]);
            part[rp * 2 + 1] += va[c] * tanhf(v.y + qp[c]);
        }
    }

    // cross-thread (over tx) reduction via smem
#pragma unroll
    for (int i = 0; i < 8; ++i) {
        int rloc = (i < 4) ? (ty * 4 + i) : (64 + ty * 4 + (i - 4));
        red[rloc * 16 + tx] = part[i];
    }
    __syncthreads();
    if (tid < 128) {
        float s = 0.f;
#pragma unroll
        for (int t = 0; t < 16; ++t) s += red[tid * 16 + t];
        g_spart[(size_t)blockIdx.x * M_TOTAL + m0 + tid] = s;
    }
}

// ---------------------------------------------------------------------------
// K3: per-batch reduce partials + softmax -> weights into d_out[32768 + b*S + s]
// 32 blocks x 256 threads, 8 elements per thread.
// ---------------------------------------------------------------------------
__global__ void k3_softmax(float* __restrict__ wout) {
    __shared__ float sm[256];
    const int b = blockIdx.x;
    const int tid = threadIdx.x;

    float v[8];
#pragma unroll
    for (int i = 0; i < 8; ++i) {
        int s = tid + i * 256;
        float t = 0.f;
#pragma unroll
        for (int p = 0; p < 8; ++p)
            t += g_spart[(size_t)p * M_TOTAL + b * S + s];
        v[i] = t;
    }
    // max reduce
    float mx = v[0];
#pragma unroll
    for (int i = 1; i < 8; ++i) mx = fmaxf(mx, v[i]);
    sm[tid] = mx;
    __syncthreads();
    for (int off = 128; off; off >>= 1) {
        if (tid < off) sm[tid] = fmaxf(sm[tid], sm[tid + off]);
        __syncthreads();
    }
    mx = sm[0];
    __syncthreads();
    // exp + sum reduce
    float sum = 0.f;
#pragma unroll
    for (int i = 0; i < 8; ++i) {
        v[i] = expf(v[i] - mx);
        sum += v[i];
    }
    sm[tid] = sum;
    __syncthreads();
    for (int off = 128; off; off >>= 1) {
        if (tid < off) sm[tid] += sm[tid + off];
        __syncthreads();
    }
    float inv = 1.0f / sm[0];
#pragma unroll
    for (int i = 0; i < 8; ++i)
        wout[b * S + tid + i * 256] = v[i] * inv;
}

// ---------------------------------------------------------------------------
// K4: partial context: cpart[sc][b][h] = sum_{s in chunk} w[b,s] * keys[b,s,h]
// grid (B, H/128, 4 s-chunks), 128 threads.
// ---------------------------------------------------------------------------
__global__ void k4_context(const float* __restrict__ keys,
                           const float* __restrict__ w) {
    const int b  = blockIdx.x;
    const int hc = blockIdx.y;
    const int sc = blockIdx.z;
    const int h  = hc * 128 + threadIdx.x;
    const float* kb = keys + ((size_t)b * S + sc * 512) * H + h;
    const float* wb = w + b * S + sc * 512;
    float acc = 0.f;
#pragma unroll 8
    for (int s = 0; s < 512; ++s)
        acc += wb[s] * kb[(size_t)s * H];
    g_cpart[sc * (B * H) + b * H + h] = acc;
}

// ---------------------------------------------------------------------------
// K5: reduce the 4 context partials into d_out[0 .. B*H)
// ---------------------------------------------------------------------------
__global__ void k5_reduce(float* __restrict__ ctx) {
    int i = blockIdx.x * 256 + threadIdx.x;
    ctx[i] = g_cpart[i] + g_cpart[B * H + i] + g_cpart[2 * B * H + i] +
             g_cpart[3 * B * H + i];
}

// ---------------------------------------------------------------------------
// launch
// ---------------------------------------------------------------------------
extern "C" void kernel_launch(void* const* d_in, const int* in_sizes, int n_in,
                              void* d_out, int out_size) {
    const float* query = (const float*)d_in[0];
    const float* keys  = (const float*)d_in[1];
    const float* Wa_w  = (const float*)d_in[2];
    const float* Wa_b  = (const float*)d_in[3];
    const float* Ua_w  = (const float*)d_in[4];
    const float* Ua_b  = (const float*)d_in[5];
    const float* Va_w  = (const float*)d_in[6];
    // Va_b (d_in[7]) is softmax-invariant -> dropped. idx (d_in[8]) unused.

    float* out = (float*)d_out;
    float* ctx_out = out;             // (B,1,H) = 32768 floats
    float* w_out   = out + B * H;     // (B,1,S) = 65536 floats

    // K1: q_proj (+ both biases folded)
    k1_qproj<<<4096, 256>>>(query, Wa_w, Wa_b, Ua_b);

    // K2: big fused GEMM + tanh + Va reduction
    dim3 g2(8, 512);
    k2_gemm_tanh<<<g2, 256>>>(keys, Ua_w, Va_w);

    // K3: softmax -> weights
    k3_softmax<<<B, 256>>>(w_out);

    // K4/K5: context = weights @ keys
    dim3 g4(B, H / 128, 4);
    k4_context<<<g4, 128>>>(keys, w_out);
    k5_reduce<<<(B * H) / 256, 256>>>(ctx_out);
}

// round 4
// speedup vs baseline: 1.2418x; 1.2418x over previous
#include <cuda_runtime.h>
#include <cuda_bf16.h>
#include <math.h>
#include <stdint.h>

typedef unsigned long long ull;

// Problem constants
#define B 32
#define S 2048
#define H 1024
#define M_TOTAL (B * S)

// ---------------------------------------------------------------------------
// Scratch (no allocations allowed -> __device__ globals)
// ---------------------------------------------------------------------------
__device__ float g_qp[B * H];            // q_proj + Wa_b + Ua_b
__device__ float g_spart[8 * M_TOTAL];   // per-n-tile partial scores
__device__ float g_cpart[4 * B * H];     // per-s-chunk partial context

// ---------------------------------------------------------------------------
// Asm helpers (base-target-safe: ldmatrix / mma.sync only)
// ---------------------------------------------------------------------------
__device__ __forceinline__ uint32_t smem_u32(const void* p) {
    uint32_t a;
    asm("{ .reg .u64 t; cvta.to.shared.u64 t, %1; cvt.u32.u64 %0, t; }"
        : "=r"(a) : "l"(p));
    return a;
}

#define STS64(smem_addr, val) \
    asm volatile("st.shared.b64 [%0], %1;" :: "r"(smem_addr), "l"(val) : "memory")

#define LDSM_X4(r, addr)                                                      \
    asm volatile("ldmatrix.sync.aligned.m8n8.x4.shared.b16 {%0,%1,%2,%3}, [%4];" \
                 : "=r"((r)[0]), "=r"((r)[1]), "=r"((r)[2]), "=r"((r)[3])     \
                 : "r"(addr))

#define LDSM_X2(r, addr)                                                      \
    asm volatile("ldmatrix.sync.aligned.m8n8.x2.shared.b16 {%0,%1}, [%2];"    \
                 : "=r"((r)[0]), "=r"((r)[1])                                 \
                 : "r"(addr))

#define MMA16816(d, a, bq)                                                    \
    asm volatile("mma.sync.aligned.m16n8k16.row.col.f32.bf16.bf16.f32 "       \
                 "{%0,%1,%2,%3}, {%4,%5,%6,%7}, {%8,%9}, {%0,%1,%2,%3};"      \
                 : "+f"((d)[0]), "+f"((d)[1]), "+f"((d)[2]), "+f"((d)[3])     \
                 : "r"((a)[0]), "r"((a)[1]), "r"((a)[2]), "r"((a)[3]),        \
                   "r"((bq)[0]), "r"((bq)[1]))

// split fp32x4 into bf16 hi quad + lo quad (each packed 8B for STS64)
__device__ __forceinline__ void split4(float4 v, ull& hv, ull& lv) {
    uint32_t h01, h23, l01, l23;
    asm("cvt.rn.bf16x2.f32 %0, %1, %2;" : "=r"(h01) : "f"(v.y), "f"(v.x));
    asm("cvt.rn.bf16x2.f32 %0, %1, %2;" : "=r"(h23) : "f"(v.w), "f"(v.z));
    float hx = __uint_as_float(h01 << 16);
    float hy = __uint_as_float(h01 & 0xFFFF0000u);
    float hz = __uint_as_float(h23 << 16);
    float hw = __uint_as_float(h23 & 0xFFFF0000u);
    asm("cvt.rn.bf16x2.f32 %0, %1, %2;" : "=r"(l01) : "f"(v.y - hy), "f"(v.x - hx));
    asm("cvt.rn.bf16x2.f32 %0, %1, %2;" : "=r"(l23) : "f"(v.w - hw), "f"(v.z - hz));
    hv = ((ull)h23 << 32) | h01;
    lv = ((ull)l23 << 32) | l01;
}

// ---------------------------------------------------------------------------
// K1: q_proj[b][o] = query[b,:] . Wa_w[o,:] + Wa_b[o] + Ua_b[o]
// ---------------------------------------------------------------------------
__global__ void k1_qproj(const float* __restrict__ query,
                         const float* __restrict__ Wa_w,
                         const float* __restrict__ Wa_b,
                         const float* __restrict__ Ua_b) {
    int gw   = (blockIdx.x * blockDim.x + threadIdx.x) >> 5;
    int lane = threadIdx.x & 31;
    int b = gw >> 10;
    int o = gw & 1023;
    const float* qr = query + b * H;
    const float* wr = Wa_w + (size_t)o * H;
    float acc = 0.f;
#pragma unroll 4
    for (int i = lane; i < H; i += 32)
        acc += qr[i] * wr[i];
#pragma unroll
    for (int off = 16; off; off >>= 1)
        acc += __shfl_xor_sync(0xFFFFFFFFu, acc, off);
    if (lane == 0)
        g_qp[gw] = acc + Wa_b[o] + Ua_b[o];
}

// ---------------------------------------------------------------------------
// K2: split-bf16 3-term mma.sync GEMM + fused tanh/Va epilogue.
// CTA tile 128(m) x 128(n), K chunk 64, double-buffered smem, 256 threads.
// grid = (8 n-tiles, 512 m-tiles).
// ---------------------------------------------------------------------------
#define NC 16                      // 1024 / 64 k-chunks
#define TILE_B 16384               // 128 rows x 128B (64 bf16)
#define STAGE_B (4 * TILE_B)       // A_hi, A_lo, B_hi, B_lo
#define SM_RED (2 * STAGE_B)       // 131072: 128 x 16 floats (8KB)
#define SM_VA (SM_RED + 8192)
#define SM_QP (SM_VA + 512)
#define K2_SMEM (SM_QP + 512)      // 140800 B

__global__ __launch_bounds__(256, 1)
void k2_mma(const float* __restrict__ keys,
            const float* __restrict__ Ua_w,
            const float* __restrict__ Va_w) {
    extern __shared__ char smem[];
    const uint32_t sb = smem_u32(smem);
    const int tid = threadIdx.x;
    const int lane = tid & 31;
    const int wid = tid >> 5;
    const int warp_m = wid >> 2;          // 0..1 (64 rows each)
    const int warp_n = wid & 3;           // 0..3 (32 cols each)
    const int n0 = blockIdx.x * 128;
    const int m0 = blockIdx.y * 128;
    const int b  = blockIdx.y >> 4;       // 16 m-tiles per batch

    // epilogue constants into smem (consumed after mainloop)
    if (tid < 128) {
        ((float*)(smem + SM_VA))[tid] = Va_w[n0 + tid];
        ((float*)(smem + SM_QP))[tid] = g_qp[b * H + n0 + tid];
    }

    // loader indexing: each thread covers (row = tid>>1, f4 = (tid&1)*8 + j)
    const int lrow = tid >> 1;
    const int lf4h = (tid & 1) * 8;
    const float* Ag = keys + (size_t)(m0 + lrow) * H;
    const float* Bg = Ua_w + (size_t)(n0 + lrow) * H;

    float acc[4][4][4];
#pragma unroll
    for (int i = 0; i < 4; ++i)
#pragma unroll
        for (int j = 0; j < 4; ++j)
#pragma unroll
            for (int k = 0; k < 4; ++k) acc[i][j][k] = 0.f;

    // ---- prologue: fill stage 0 ----
#pragma unroll
    for (int j = 0; j < 8; ++j) {
        const int f4 = lf4h + j;
        const uint32_t sw = (uint32_t)lrow * 128 +
                            ((((uint32_t)f4 >> 1) ^ (lrow & 7)) << 4) +
                            (f4 & 1) * 8;
        ull hv, lv;
        float4 va4 = *(const float4*)(Ag + f4 * 4);
        split4(va4, hv, lv);
        STS64(sb + sw, hv);
        STS64(sb + TILE_B + sw, lv);
        float4 vb4 = *(const float4*)(Bg + f4 * 4);
        split4(vb4, hv, lv);
        STS64(sb + 2 * TILE_B + sw, hv);
        STS64(sb + 3 * TILE_B + sw, lv);
    }
    __syncthreads();

    // ---- mainloop ----
    for (int c = 0; c < NC; ++c) {
        const uint32_t cur = sb + (uint32_t)(c & 1) * STAGE_B;
        const uint32_t nxt = sb + (uint32_t)((c + 1) & 1) * STAGE_B;
        const int k0n = (c + 1) * 64;

#pragma unroll
        for (int ks = 0; ks < 4; ++ks) {
            // interleave next-stage loads (2 A + 2 B float4 per quarter)
            if (c + 1 < NC) {
#pragma unroll
                for (int j = 2 * ks; j < 2 * ks + 2; ++j) {
                    const int f4 = lf4h + j;
                    const uint32_t sw = (uint32_t)lrow * 128 +
                                        ((((uint32_t)f4 >> 1) ^ (lrow & 7)) << 4) +
                                        (f4 & 1) * 8;
                    ull hv, lv;
                    float4 va4 = *(const float4*)(Ag + k0n + f4 * 4);
                    split4(va4, hv, lv);
                    STS64(nxt + sw, hv);
                    STS64(nxt + TILE_B + sw, lv);
                    float4 vb4 = *(const float4*)(Bg + k0n + f4 * 4);
                    split4(vb4, hv, lv);
                    STS64(nxt + 2 * TILE_B + sw, hv);
                    STS64(nxt + 3 * TILE_B + sw, lv);
                }
            }

            // ldmatrix fragments
            uint32_t ah[4][4], al[4][4];
#pragma unroll
            for (int fm = 0; fm < 4; ++fm) {
                const int row = warp_m * 64 + fm * 16 + (lane & 15);
                const int ch = ks * 2 + (lane >> 4);
                const uint32_t ad = cur + (uint32_t)row * 128 +
                                    (((uint32_t)(ch ^ (row & 7))) << 4);
                LDSM_X4(ah[fm], ad);
                LDSM_X4(al[fm], ad + TILE_B);
            }
            uint32_t bh[4][2], bl[4][2];
#pragma unroll
            for (int fn = 0; fn < 4; ++fn) {
                const int rn = warp_n * 32 + fn * 8 + (lane & 7);
                const int ch = ks * 2 + ((lane >> 3) & 1);
                const uint32_t bd = cur + 2 * TILE_B + (uint32_t)rn * 128 +
                                    (((uint32_t)(ch ^ (rn & 7))) << 4);
                LDSM_X2(bh[fn], bd);
                LDSM_X2(bl[fn], bd + TILE_B);
            }

            // 3-term MMAs: hi*hi + hi*lo + lo*hi
#pragma unroll
            for (int fm = 0; fm < 4; ++fm) {
#pragma unroll
                for (int fn = 0; fn < 4; ++fn) {
                    MMA16816(acc[fm][fn], ah[fm], bh[fn]);
                    MMA16816(acc[fm][fn], ah[fm], bl[fn]);
                    MMA16816(acc[fm][fn], al[fm], bh[fn]);
                }
            }
        }
        __syncthreads();
    }

    // ---- fused epilogue: tanh + Va dot, reduce over columns ----
    const float* sva = (const float*)(smem + SM_VA);
    const float* sqp = (const float*)(smem + SM_QP);
    float* red = (float*)(smem + SM_RED);
    const int quad = lane & 3;
    const int ln4 = lane >> 2;
    const int slot = warp_n * 4 + quad;

#pragma unroll
    for (int fm = 0; fm < 4; ++fm) {
        float rv0 = 0.f, rv1 = 0.f;
#pragma unroll
        for (int fn = 0; fn < 4; ++fn) {
            const int c0 = warp_n * 32 + fn * 8 + quad * 2;
            const int c1 = c0 + 1;
            rv0 += sva[c0] * tanhf(acc[fm][fn][0] + sqp[c0]);
            rv0 += sva[c1] * tanhf(acc[fm][fn][1] + sqp[c1]);
            rv1 += sva[c0] * tanhf(acc[fm][fn][2] + sqp[c0]);
            rv1 += sva[c1] * tanhf(acc[fm][fn][3] + sqp[c1]);
        }
        const int rowA = warp_m * 64 + fm * 16 + ln4;
        red[rowA * 16 + slot] = rv0;
        red[(rowA + 8) * 16 + slot] = rv1;
    }
    __syncthreads();
    if (tid < 128) {
        float s = 0.f;
#pragma unroll
        for (int t = 0; t < 16; ++t) s += red[tid * 16 + t];
        g_spart[(size_t)blockIdx.x * M_TOTAL + m0 + tid] = s;
    }
}

// ---------------------------------------------------------------------------
// K3: reduce 8 partials per row + softmax -> weights
// ---------------------------------------------------------------------------
__global__ void k3_softmax(float* __restrict__ wout) {
    __shared__ float sm[256];
    const int b = blockIdx.x;
    const int tid = threadIdx.x;

    float v[8];
#pragma unroll
    for (int i = 0; i < 8; ++i) {
        int s = tid + i * 256;
        float t = 0.f;
#pragma unroll
        for (int p = 0; p < 8; ++p)
            t += g_spart[(size_t)p * M_TOTAL + b * S + s];
        v[i] = t;
    }
    float mx = v[0];
#pragma unroll
    for (int i = 1; i < 8; ++i) mx = fmaxf(mx, v[i]);
    sm[tid] = mx;
    __syncthreads();
    for (int off = 128; off; off >>= 1) {
        if (tid < off) sm[tid] = fmaxf(sm[tid], sm[tid + off]);
        __syncthreads();
    }
    mx = sm[0];
    __syncthreads();
    float sum = 0.f;
#pragma unroll
    for (int i = 0; i < 8; ++i) {
        v[i] = expf(v[i] - mx);
        sum += v[i];
    }
    sm[tid] = sum;
    __syncthreads();
    for (int off = 128; off; off >>= 1) {
        if (tid < off) sm[tid] += sm[tid + off];
        __syncthreads();
    }
    float inv = 1.0f / sm[0];
#pragma unroll
    for (int i = 0; i < 8; ++i)
        wout[b * S + tid + i * 256] = v[i] * inv;
}

// ---------------------------------------------------------------------------
// K4: partial context GEMV
// ---------------------------------------------------------------------------
__global__ void k4_context(const float* __restrict__ keys,
                           const float* __restrict__ w) {
    const int b  = blockIdx.x;
    const int hc = blockIdx.y;
    const int sc = blockIdx.z;
    const int h  = hc * 128 + threadIdx.x;
    const float* kb = keys + ((size_t)b * S + sc * 512) * H + h;
    const float* wb = w + b * S + sc * 512;
    float acc = 0.f;
#pragma unroll 8
    for (int s = 0; s < 512; ++s)
        acc += wb[s] * kb[(size_t)s * H];
    g_cpart[sc * (B * H) + b * H + h] = acc;
}

// ---------------------------------------------------------------------------
// K5: reduce context partials
// ---------------------------------------------------------------------------
__global__ void k5_reduce(float* __restrict__ ctx) {
    int i = blockIdx.x * 256 + threadIdx.x;
    ctx[i] = g_cpart[i] + g_cpart[B * H + i] + g_cpart[2 * B * H + i] +
             g_cpart[3 * B * H + i];
}

// ---------------------------------------------------------------------------
// launch
// ---------------------------------------------------------------------------
extern "C" void kernel_launch(void* const* d_in, const int* in_sizes, int n_in,
                              void* d_out, int out_size) {
    const float* query = (const float*)d_in[0];
    const float* keys  = (const float*)d_in[1];
    const float* Wa_w  = (const float*)d_in[2];
    const float* Wa_b  = (const float*)d_in[3];
    const float* Ua_w  = (const float*)d_in[4];
    const float* Ua_b  = (const float*)d_in[5];
    const float* Va_w  = (const float*)d_in[6];
    // Va_b (d_in[7]) softmax-invariant; idx (d_in[8]) unused.

    float* out = (float*)d_out;
    float* ctx_out = out;             // (B,1,H)
    float* w_out   = out + B * H;     // (B,1,S)

    static int smem_set = 0;
    if (!smem_set) {
        cudaFuncSetAttribute(k2_mma, cudaFuncAttributeMaxDynamicSharedMemorySize,
                             K2_SMEM);
        smem_set = 1;
    }

    k1_qproj<<<4096, 256>>>(query, Wa_w, Wa_b, Ua_b);

    dim3 g2(8, 512);
    k2_mma<<<g2, 256, K2_SMEM>>>(keys, Ua_w, Va_w);

    k3_softmax<<<B, 256>>>(w_out);

    dim3 g4(B, H / 128, 4);
    k4_context<<<g4, 128>>>(keys, w_out);
    k5_reduce<<<(B * H) / 256, 256>>>(ctx_out);
}

// round 5
// speedup vs baseline: 1.2434x; 1.0013x over previous
#include <cuda_runtime.h>
#include <cuda_bf16.h>
#include <math.h>
#include <stdint.h>

typedef unsigned long long ull;

// Problem constants
#define B 32
#define S 2048
#define H 1024
#define M_TOTAL (B * S)

// ---------------------------------------------------------------------------
// Scratch (no allocations allowed -> __device__ globals)
// ---------------------------------------------------------------------------
__device__ float g_qp[B * H];            // q_proj + Wa_b + Ua_b
__device__ float g_spart[8 * M_TOTAL];   // per-n-tile partial scores
__device__ float g_cpart[4 * B * H];     // per-s-chunk partial context

// ---------------------------------------------------------------------------
// Asm helpers (base-target-safe: ldmatrix / mma.sync only)
// ---------------------------------------------------------------------------
__device__ __forceinline__ uint32_t smem_u32(const void* p) {
    uint32_t a;
    asm("{ .reg .u64 t; cvta.to.shared.u64 t, %1; cvt.u32.u64 %0, t; }"
        : "=r"(a) : "l"(p));
    return a;
}

#define STS64(smem_addr, val) \
    asm volatile("st.shared.b64 [%0], %1;" :: "r"(smem_addr), "l"(val) : "memory")

#define LDSM_X4(r, addr)                                                      \
    asm volatile("ldmatrix.sync.aligned.m8n8.x4.shared.b16 {%0,%1,%2,%3}, [%4];" \
                 : "=r"((r)[0]), "=r"((r)[1]), "=r"((r)[2]), "=r"((r)[3])     \
                 : "r"(addr))

#define LDSM_X2(r, addr)                                                      \
    asm volatile("ldmatrix.sync.aligned.m8n8.x2.shared.b16 {%0,%1}, [%2];"    \
                 : "=r"((r)[0]), "=r"((r)[1])                                 \
                 : "r"(addr))

#define MMA16816(d, a, bq)                                                    \
    asm volatile("mma.sync.aligned.m16n8k16.row.col.f32.bf16.bf16.f32 "       \
                 "{%0,%1,%2,%3}, {%4,%5,%6,%7}, {%8,%9}, {%0,%1,%2,%3};"      \
                 : "+f"((d)[0]), "+f"((d)[1]), "+f"((d)[2]), "+f"((d)[3])     \
                 : "r"((a)[0]), "r"((a)[1]), "r"((a)[2]), "r"((a)[3]),        \
                   "r"((bq)[0]), "r"((bq)[1]))

// split fp32x4 into bf16 hi quad + lo quad (each packed 8B for STS64)
__device__ __forceinline__ void split4(float4 v, ull& hv, ull& lv) {
    uint32_t h01, h23, l01, l23;
    asm("cvt.rn.bf16x2.f32 %0, %1, %2;" : "=r"(h01) : "f"(v.y), "f"(v.x));
    asm("cvt.rn.bf16x2.f32 %0, %1, %2;" : "=r"(h23) : "f"(v.w), "f"(v.z));
    float hx = __uint_as_float(h01 << 16);
    float hy = __uint_as_float(h01 & 0xFFFF0000u);
    float hz = __uint_as_float(h23 << 16);
    float hw = __uint_as_float(h23 & 0xFFFF0000u);
    asm("cvt.rn.bf16x2.f32 %0, %1, %2;" : "=r"(l01) : "f"(v.y - hy), "f"(v.x - hx));
    asm("cvt.rn.bf16x2.f32 %0, %1, %2;" : "=r"(l23) : "f"(v.w - hw), "f"(v.z - hz));
    hv = ((ull)h23 << 32) | h01;
    lv = ((ull)l23 << 32) | l01;
}

// ---------------------------------------------------------------------------
// K1: q_proj[b][o] = query[b,:] . Wa_w[o,:] + Wa_b[o] + Ua_b[o]
// ---------------------------------------------------------------------------
__global__ void k1_qproj(const float* __restrict__ query,
                         const float* __restrict__ Wa_w,
                         const float* __restrict__ Wa_b,
                         const float* __restrict__ Ua_b) {
    int gw   = (blockIdx.x * blockDim.x + threadIdx.x) >> 5;
    int lane = threadIdx.x & 31;
    int b = gw >> 10;
    int o = gw & 1023;
    const float* qr = query + b * H;
    const float* wr = Wa_w + (size_t)o * H;
    float acc = 0.f;
#pragma unroll 4
    for (int i = lane; i < H; i += 32)
        acc += qr[i] * wr[i];
#pragma unroll
    for (int off = 16; off; off >>= 1)
        acc += __shfl_xor_sync(0xFFFFFFFFu, acc, off);
    if (lane == 0)
        g_qp[gw] = acc + Wa_b[o] + Ua_b[o];
}

// ---------------------------------------------------------------------------
// K2: split-bf16 3-term mma.sync GEMM + fused tanh/Va epilogue.
// CTA tile 128(m) x 128(n), K chunk 64, double-buffered smem, 256 threads.
// grid = (8 n-tiles, 512 m-tiles).
// ---------------------------------------------------------------------------
#define NC 16                      // 1024 / 64 k-chunks
#define TILE_B 16384               // 128 rows x 128B (64 bf16)
#define STAGE_B (4 * TILE_B)       // A_hi, A_lo, B_hi, B_lo
#define SM_RED (2 * STAGE_B)       // 131072: 128 x 16 floats (8KB)
#define SM_VA (SM_RED + 8192)
#define SM_QP (SM_VA + 512)
#define K2_SMEM (SM_QP + 512)      // 140800 B

__global__ __launch_bounds__(256, 1)
void k2_mma(const float* __restrict__ keys,
            const float* __restrict__ Ua_w,
            const float* __restrict__ Va_w) {
    extern __shared__ char smem[];
    const uint32_t sb = smem_u32(smem);
    const int tid = threadIdx.x;
    const int lane = tid & 31;
    const int wid = tid >> 5;
    const int warp_m = wid >> 2;          // 0..1 (64 rows each)
    const int warp_n = wid & 3;           // 0..3 (32 cols each)
    const int n0 = blockIdx.x * 128;
    const int m0 = blockIdx.y * 128;
    const int b  = blockIdx.y >> 4;       // 16 m-tiles per batch

    // epilogue constants into smem (consumed after mainloop)
    if (tid < 128) {
        ((float*)(smem + SM_VA))[tid] = Va_w[n0 + tid];
        ((float*)(smem + SM_QP))[tid] = g_qp[b * H + n0 + tid];
    }

    // loader indexing: each thread covers (row = tid>>1, f4 = (tid&1)*8 + j)
    const int lrow = tid >> 1;
    const int lf4h = (tid & 1) * 8;
    const float* Ag = keys + (size_t)(m0 + lrow) * H;
    const float* Bg = Ua_w + (size_t)(n0 + lrow) * H;

    float acc[4][4][4];
#pragma unroll
    for (int i = 0; i < 4; ++i)
#pragma unroll
        for (int j = 0; j < 4; ++j)
#pragma unroll
            for (int k = 0; k < 4; ++k) acc[i][j][k] = 0.f;

    // ---- prologue: fill stage 0 ----
#pragma unroll
    for (int j = 0; j < 8; ++j) {
        const int f4 = lf4h + j;
        const uint32_t sw = (uint32_t)lrow * 128 +
                            ((((uint32_t)f4 >> 1) ^ (lrow & 7)) << 4) +
                            (f4 & 1) * 8;
        ull hv, lv;
        float4 va4 = *(const float4*)(Ag + f4 * 4);
        split4(va4, hv, lv);
        STS64(sb + sw, hv);
        STS64(sb + TILE_B + sw, lv);
        float4 vb4 = *(const float4*)(Bg + f4 * 4);
        split4(vb4, hv, lv);
        STS64(sb + 2 * TILE_B + sw, hv);
        STS64(sb + 3 * TILE_B + sw, lv);
    }
    __syncthreads();

    // ---- mainloop ----
    for (int c = 0; c < NC; ++c) {
        const uint32_t cur = sb + (uint32_t)(c & 1) * STAGE_B;
        const uint32_t nxt = sb + (uint32_t)((c + 1) & 1) * STAGE_B;
        const int k0n = (c + 1) * 64;

#pragma unroll
        for (int ks = 0; ks < 4; ++ks) {
            // interleave next-stage loads (2 A + 2 B float4 per quarter)
            if (c + 1 < NC) {
#pragma unroll
                for (int j = 2 * ks; j < 2 * ks + 2; ++j) {
                    const int f4 = lf4h + j;
                    const uint32_t sw = (uint32_t)lrow * 128 +
                                        ((((uint32_t)f4 >> 1) ^ (lrow & 7)) << 4) +
                                        (f4 & 1) * 8;
                    ull hv, lv;
                    float4 va4 = *(const float4*)(Ag + k0n + f4 * 4);
                    split4(va4, hv, lv);
                    STS64(nxt + sw, hv);
                    STS64(nxt + TILE_B + sw, lv);
                    float4 vb4 = *(const float4*)(Bg + k0n + f4 * 4);
                    split4(vb4, hv, lv);
                    STS64(nxt + 2 * TILE_B + sw, hv);
                    STS64(nxt + 3 * TILE_B + sw, lv);
                }
            }

            // ldmatrix fragments
            uint32_t ah[4][4], al[4][4];
#pragma unroll
            for (int fm = 0; fm < 4; ++fm) {
                const int row = warp_m * 64 + fm * 16 + (lane & 15);
                const int ch = ks * 2 + (lane >> 4);
                const uint32_t ad = cur + (uint32_t)row * 128 +
                                    (((uint32_t)(ch ^ (row & 7))) << 4);
                LDSM_X4(ah[fm], ad);
                LDSM_X4(al[fm], ad + TILE_B);
            }
            uint32_t bh[4][2], bl[4][2];
#pragma unroll
            for (int fn = 0; fn < 4; ++fn) {
                const int rn = warp_n * 32 + fn * 8 + (lane & 7);
                const int ch = ks * 2 + ((lane >> 3) & 1);
                const uint32_t bd = cur + 2 * TILE_B + (uint32_t)rn * 128 +
                                    (((uint32_t)(ch ^ (rn & 7))) << 4);
                LDSM_X2(bh[fn], bd);
                LDSM_X2(bl[fn], bd + TILE_B);
            }

            // 3-term MMAs: hi*hi + hi*lo + lo*hi
#pragma unroll
            for (int fm = 0; fm < 4; ++fm) {
#pragma unroll
                for (int fn = 0; fn < 4; ++fn) {
                    MMA16816(acc[fm][fn], ah[fm], bh[fn]);
                    MMA16816(acc[fm][fn], ah[fm], bl[fn]);
                    MMA16816(acc[fm][fn], al[fm], bh[fn]);
                }
            }
        }
        __syncthreads();
    }

    // ---- fused epilogue: tanh + Va dot, reduce over columns ----
    const float* sva = (const float*)(smem + SM_VA);
    const float* sqp = (const float*)(smem + SM_QP);
    float* red = (float*)(smem + SM_RED);
    const int quad = lane & 3;
    const int ln4 = lane >> 2;
    const int slot = warp_n * 4 + quad;

#pragma unroll
    for (int fm = 0; fm < 4; ++fm) {
        float rv0 = 0.f, rv1 = 0.f;
#pragma unroll
        for (int fn = 0; fn < 4; ++fn) {
            const int c0 = warp_n * 32 + fn * 8 + quad * 2;
            const int c1 = c0 + 1;
            rv0 += sva[c0] * tanhf(acc[fm][fn][0] + sqp[c0]);
            rv0 += sva[c1] * tanhf(acc[fm][fn][1] + sqp[c1]);
            rv1 += sva[c0] * tanhf(acc[fm][fn][2] + sqp[c0]);
            rv1 += sva[c1] * tanhf(acc[fm][fn][3] + sqp[c1]);
        }
        const int rowA = warp_m * 64 + fm * 16 + ln4;
        red[rowA * 16 + slot] = rv0;
        red[(rowA + 8) * 16 + slot] = rv1;
    }
    __syncthreads();
    if (tid < 128) {
        float s = 0.f;
#pragma unroll
        for (int t = 0; t < 16; ++t) s += red[tid * 16 + t];
        g_spart[(size_t)blockIdx.x * M_TOTAL + m0 + tid] = s;
    }
}

// ---------------------------------------------------------------------------
// K3: reduce 8 partials per row + softmax -> weights
// ---------------------------------------------------------------------------
__global__ void k3_softmax(float* __restrict__ wout) {
    __shared__ float sm[256];
    const int b = blockIdx.x;
    const int tid = threadIdx.x;

    float v[8];
#pragma unroll
    for (int i = 0; i < 8; ++i) {
        int s = tid + i * 256;
        float t = 0.f;
#pragma unroll
        for (int p = 0; p < 8; ++p)
            t += g_spart[(size_t)p * M_TOTAL + b * S + s];
        v[i] = t;
    }
    float mx = v[0];
#pragma unroll
    for (int i = 1; i < 8; ++i) mx = fmaxf(mx, v[i]);
    sm[tid] = mx;
    __syncthreads();
    for (int off = 128; off; off >>= 1) {
        if (tid < off) sm[tid] = fmaxf(sm[tid], sm[tid + off]);
        __syncthreads();
    }
    mx = sm[0];
    __syncthreads();
    float sum = 0.f;
#pragma unroll
    for (int i = 0; i < 8; ++i) {
        v[i] = expf(v[i] - mx);
        sum += v[i];
    }
    sm[tid] = sum;
    __syncthreads();
    for (int off = 128; off; off >>= 1) {
        if (tid < off) sm[tid] += sm[tid + off];
        __syncthreads();
    }
    float inv = 1.0f / sm[0];
#pragma unroll
    for (int i = 0; i < 8; ++i)
        wout[b * S + tid + i * 256] = v[i] * inv;
}

// ---------------------------------------------------------------------------
// K4: partial context GEMV
// ---------------------------------------------------------------------------
__global__ void k4_context(const float* __restrict__ keys,
                           const float* __restrict__ w) {
    const int b  = blockIdx.x;
    const int hc = blockIdx.y;
    const int sc = blockIdx.z;
    const int h  = hc * 128 + threadIdx.x;
    const float* kb = keys + ((size_t)b * S + sc * 512) * H + h;
    const float* wb = w + b * S + sc * 512;
    float acc = 0.f;
#pragma unroll 8
    for (int s = 0; s < 512; ++s)
        acc += wb[s] * kb[(size_t)s * H];
    g_cpart[sc * (B * H) + b * H + h] = acc;
}

// ---------------------------------------------------------------------------
// K5: reduce context partials
// ---------------------------------------------------------------------------
__global__ void k5_reduce(float* __restrict__ ctx) {
    int i = blockIdx.x * 256 + threadIdx.x;
    ctx[i] = g_cpart[i] + g_cpart[B * H + i] + g_cpart[2 * B * H + i] +
             g_cpart[3 * B * H + i];
}

// ---------------------------------------------------------------------------
// launch
// ---------------------------------------------------------------------------
extern "C" void kernel_launch(void* const* d_in, const int* in_sizes, int n_in,
                              void* d_out, int out_size) {
    const float* query = (const float*)d_in[0];
    const float* keys  = (const float*)d_in[1];
    const float* Wa_w  = (const float*)d_in[2];
    const float* Wa_b  = (const float*)d_in[3];
    const float* Ua_w  = (const float*)d_in[4];
    const float* Ua_b  = (const float*)d_in[5];
    const float* Va_w  = (const float*)d_in[6];
    // Va_b (d_in[7]) softmax-invariant; idx (d_in[8]) unused.

    float* out = (float*)d_out;
    float* ctx_out = out;             // (B,1,H)
    float* w_out   = out + B * H;     // (B,1,S)

    static int smem_set = 0;
    if (!smem_set) {
        cudaFuncSetAttribute(k2_mma, cudaFuncAttributeMaxDynamicSharedMemorySize,
                             K2_SMEM);
        smem_set = 1;
    }

    k1_qproj<<<4096, 256>>>(query, Wa_w, Wa_b, Ua_b);

    dim3 g2(8, 512);
    k2_mma<<<g2, 256, K2_SMEM>>>(keys, Ua_w, Va_w);

    k3_softmax<<<B, 256>>>(w_out);

    dim3 g4(B, H / 128, 4);
    k4_context<<<g4, 128>>>(keys, w_out);
    k5_reduce<<<(B * H) / 256, 256>>>(ctx_out);
}

// round 6
// speedup vs baseline: 1.3368x; 1.0751x over previous
#include <cuda_runtime.h>
#include <cuda_bf16.h>
#include <cuda_fp16.h>
#include <math.h>
#include <stdint.h>

typedef unsigned long long ull;

// Problem constants
#define B 32
#define S 2048
#define H 1024
#define M_TOTAL (B * S)

// ---------------------------------------------------------------------------
// Scratch (no allocations allowed -> __device__ globals)
// ---------------------------------------------------------------------------
__device__ float g_qp[B * H];            // q_proj + Wa_b + Ua_b
__device__ float g_spart[8 * M_TOTAL];   // per-n-tile partial scores
__device__ float g_cpart[4 * B * H];     // per-s-chunk partial context

// ---------------------------------------------------------------------------
// Asm helpers (base-target-safe: ldmatrix / mma.sync only)
// ---------------------------------------------------------------------------
__device__ __forceinline__ uint32_t smem_u32(const void* p) {
    uint32_t a;
    asm("{ .reg .u64 t; cvta.to.shared.u64 t, %1; cvt.u32.u64 %0, t; }"
        : "=r"(a) : "l"(p));
    return a;
}

#define STS64(smem_addr, val) \
    asm volatile("st.shared.b64 [%0], %1;" :: "r"(smem_addr), "l"(val) : "memory")

#define LDSM_X4(r, addr)                                                      \
    asm volatile("ldmatrix.sync.aligned.m8n8.x4.shared.b16 {%0,%1,%2,%3}, [%4];" \
                 : "=r"((r)[0]), "=r"((r)[1]), "=r"((r)[2]), "=r"((r)[3])     \
                 : "r"(addr))

#define LDSM_X2(r, addr)                                                      \
    asm volatile("ldmatrix.sync.aligned.m8n8.x2.shared.b16 {%0,%1}, [%2];"    \
                 : "=r"((r)[0]), "=r"((r)[1])                                 \
                 : "r"(addr))

#define MMAF16(d, a, bq)                                                      \
    asm volatile("mma.sync.aligned.m16n8k16.row.col.f32.f16.f16.f32 "         \
                 "{%0,%1,%2,%3}, {%4,%5,%6,%7}, {%8,%9}, {%0,%1,%2,%3};"      \
                 : "+f"((d)[0]), "+f"((d)[1]), "+f"((d)[2]), "+f"((d)[3])     \
                 : "r"((a)[0]), "r"((a)[1]), "r"((a)[2]), "r"((a)[3]),        \
                   "r"((bq)[0]), "r"((bq)[1]))

// split fp32x4 into fp16 hi quad + fp16 lo quad (each packed 8B for STS64)
__device__ __forceinline__ void split4h(float4 v, ull& hv, ull& lv) {
    __half2 h01 = __floats2half2_rn(v.x, v.y);
    __half2 h23 = __floats2half2_rn(v.z, v.w);
    float2 f01 = __half22float2(h01);
    float2 f23 = __half22float2(h23);
    __half2 l01 = __floats2half2_rn(v.x - f01.x, v.y - f01.y);
    __half2 l23 = __floats2half2_rn(v.z - f23.x, v.w - f23.y);
    hv = ((ull)*(uint32_t*)&h23 << 32) | *(uint32_t*)&h01;
    lv = ((ull)*(uint32_t*)&l23 << 32) | *(uint32_t*)&l01;
}

// convert fp32x4 -> fp16 quad (8B)
__device__ __forceinline__ ull cvt4h(float4 v) {
    __half2 h01 = __floats2half2_rn(v.x, v.y);
    __half2 h23 = __floats2half2_rn(v.z, v.w);
    return ((ull)*(uint32_t*)&h23 << 32) | *(uint32_t*)&h01;
}

// ---------------------------------------------------------------------------
// K1: q_proj[b][o] = query[b,:] . Wa_w[o,:] + Wa_b[o] + Ua_b[o]
// ---------------------------------------------------------------------------
__global__ void k1_qproj(const float* __restrict__ query,
                         const float* __restrict__ Wa_w,
                         const float* __restrict__ Wa_b,
                         const float* __restrict__ Ua_b) {
    int gw   = (blockIdx.x * blockDim.x + threadIdx.x) >> 5;
    int lane = threadIdx.x & 31;
    int b = gw >> 10;
    int o = gw & 1023;
    const float* qr = query + b * H;
    const float* wr = Wa_w + (size_t)o * H;
    float acc = 0.f;
#pragma unroll 4
    for (int i = lane; i < H; i += 32)
        acc += qr[i] * wr[i];
#pragma unroll
    for (int off = 16; off; off >>= 1)
        acc += __shfl_xor_sync(0xFFFFFFFFu, acc, off);
    if (lane == 0)
        g_qp[gw] = acc + Wa_b[o] + Ua_b[o];
}

// ---------------------------------------------------------------------------
// K2: asymmetric fp16 2-term mma.sync GEMM + fused tanh/Va epilogue.
//   keys = Ah + Al (fp16 2-limb), Ua in single fp16 (values are U(+-1/32),
//   fp16 repr err 2^-11 -> well inside 1e-3 output tolerance).
//   C = Ah*B + Al*B, fp32 accum.
// CTA tile 128(m) x 128(n), K chunk 64, double-buffered smem, 256 threads.
// grid = (8 n-tiles, 512 m-tiles).
// ---------------------------------------------------------------------------
#define NC 16                      // 1024 / 64 k-chunks
#define TILE_B 16384               // 128 rows x 128B (64 fp16)
#define STAGE_B (3 * TILE_B)       // A_hi, A_lo, B
#define SM_RED (2 * STAGE_B)       // 98304: 128 x 16 floats (8KB)
#define SM_VA (SM_RED + 8192)
#define SM_QP (SM_VA + 512)
#define K2_SMEM (SM_QP + 512)      // 107520 B

__global__ __launch_bounds__(256, 1)
void k2_mma(const float* __restrict__ keys,
            const float* __restrict__ Ua_w,
            const float* __restrict__ Va_w) {
    extern __shared__ char smem[];
    const uint32_t sb = smem_u32(smem);
    const int tid = threadIdx.x;
    const int lane = tid & 31;
    const int wid = tid >> 5;
    const int warp_m = wid >> 2;          // 0..1 (64 rows each)
    const int warp_n = wid & 3;           // 0..3 (32 cols each)
    const int n0 = blockIdx.x * 128;
    const int m0 = blockIdx.y * 128;
    const int b  = blockIdx.y >> 4;       // 16 m-tiles per batch

    // epilogue constants into smem (consumed after mainloop)
    if (tid < 128) {
        ((float*)(smem + SM_VA))[tid] = Va_w[n0 + tid];
        ((float*)(smem + SM_QP))[tid] = g_qp[b * H + n0 + tid];
    }

    // loader indexing: each thread covers (row = tid>>1, f4 = (tid&1)*8 + j)
    const int lrow = tid >> 1;
    const int lf4h = (tid & 1) * 8;
    const float* Ag = keys + (size_t)(m0 + lrow) * H;
    const float* Bg = Ua_w + (size_t)(n0 + lrow) * H;

    float acc[4][4][4];
#pragma unroll
    for (int i = 0; i < 4; ++i)
#pragma unroll
        for (int j = 0; j < 4; ++j)
#pragma unroll
            for (int k = 0; k < 4; ++k) acc[i][j][k] = 0.f;

    // ---- prologue: fill stage 0 ----
#pragma unroll
    for (int j = 0; j < 8; ++j) {
        const int f4 = lf4h + j;
        const uint32_t sw = (uint32_t)lrow * 128 +
                            ((((uint32_t)f4 >> 1) ^ (lrow & 7)) << 4) +
                            (f4 & 1) * 8;
        ull hv, lv;
        float4 va4 = *(const float4*)(Ag + f4 * 4);
        split4h(va4, hv, lv);
        STS64(sb + sw, hv);
        STS64(sb + TILE_B + sw, lv);
        float4 vb4 = *(const float4*)(Bg + f4 * 4);
        STS64(sb + 2 * TILE_B + sw, cvt4h(vb4));
    }
    __syncthreads();

    // ---- mainloop ----
    for (int c = 0; c < NC; ++c) {
        const uint32_t cur = sb + (uint32_t)(c & 1) * STAGE_B;
        const uint32_t nxt = sb + (uint32_t)((c + 1) & 1) * STAGE_B;
        const int k0n = (c + 1) * 64;

#pragma unroll
        for (int ks = 0; ks < 4; ++ks) {
            // interleave next-stage loads (2 A + 2 B float4 per quarter)
            if (c + 1 < NC) {
#pragma unroll
                for (int j = 2 * ks; j < 2 * ks + 2; ++j) {
                    const int f4 = lf4h + j;
                    const uint32_t sw = (uint32_t)lrow * 128 +
                                        ((((uint32_t)f4 >> 1) ^ (lrow & 7)) << 4) +
                                        (f4 & 1) * 8;
                    ull hv, lv;
                    float4 va4 = *(const float4*)(Ag + k0n + f4 * 4);
                    split4h(va4, hv, lv);
                    STS64(nxt + sw, hv);
                    STS64(nxt + TILE_B + sw, lv);
                    float4 vb4 = *(const float4*)(Bg + k0n + f4 * 4);
                    STS64(nxt + 2 * TILE_B + sw, cvt4h(vb4));
                }
            }

            // ldmatrix fragments
            uint32_t ah[4][4], al[4][4];
#pragma unroll
            for (int fm = 0; fm < 4; ++fm) {
                const int row = warp_m * 64 + fm * 16 + (lane & 15);
                const int ch = ks * 2 + (lane >> 4);
                const uint32_t ad = cur + (uint32_t)row * 128 +
                                    (((uint32_t)(ch ^ (row & 7))) << 4);
                LDSM_X4(ah[fm], ad);
                LDSM_X4(al[fm], ad + TILE_B);
            }
            uint32_t bh[4][2];
#pragma unroll
            for (int fn = 0; fn < 4; ++fn) {
                const int rn = warp_n * 32 + fn * 8 + (lane & 7);
                const int ch = ks * 2 + ((lane >> 3) & 1);
                const uint32_t bd = cur + 2 * TILE_B + (uint32_t)rn * 128 +
                                    (((uint32_t)(ch ^ (rn & 7))) << 4);
                LDSM_X2(bh[fn], bd);
            }

            // 2-term MMAs: Ah*B + Al*B
#pragma unroll
            for (int fm = 0; fm < 4; ++fm) {
#pragma unroll
                for (int fn = 0; fn < 4; ++fn) {
                    MMAF16(acc[fm][fn], ah[fm], bh[fn]);
                    MMAF16(acc[fm][fn], al[fm], bh[fn]);
                }
            }
        }
        __syncthreads();
    }

    // ---- fused epilogue: tanh + Va dot, reduce over columns ----
    const float* sva = (const float*)(smem + SM_VA);
    const float* sqp = (const float*)(smem + SM_QP);
    float* red = (float*)(smem + SM_RED);
    const int quad = lane & 3;
    const int ln4 = lane >> 2;
    const int slot = warp_n * 4 + quad;

#pragma unroll
    for (int fm = 0; fm < 4; ++fm) {
        float rv0 = 0.f, rv1 = 0.f;
#pragma unroll
        for (int fn = 0; fn < 4; ++fn) {
            const int c0 = warp_n * 32 + fn * 8 + quad * 2;
            const int c1 = c0 + 1;
            rv0 += sva[c0] * tanhf(acc[fm][fn][0] + sqp[c0]);
            rv0 += sva[c1] * tanhf(acc[fm][fn][1] + sqp[c1]);
            rv1 += sva[c0] * tanhf(acc[fm][fn][2] + sqp[c0]);
            rv1 += sva[c1] * tanhf(acc[fm][fn][3] + sqp[c1]);
        }
        const int rowA = warp_m * 64 + fm * 16 + ln4;
        red[rowA * 16 + slot] = rv0;
        red[(rowA + 8) * 16 + slot] = rv1;
    }
    __syncthreads();
    if (tid < 128) {
        float s = 0.f;
#pragma unroll
        for (int t = 0; t < 16; ++t) s += red[tid * 16 + t];
        g_spart[(size_t)blockIdx.x * M_TOTAL + m0 + tid] = s;
    }
}

// ---------------------------------------------------------------------------
// K3: reduce 8 partials per row + softmax -> weights
// ---------------------------------------------------------------------------
__global__ void k3_softmax(float* __restrict__ wout) {
    __shared__ float sm[256];
    const int b = blockIdx.x;
    const int tid = threadIdx.x;

    float v[8];
#pragma unroll
    for (int i = 0; i < 8; ++i) {
        int s = tid + i * 256;
        float t = 0.f;
#pragma unroll
        for (int p = 0; p < 8; ++p)
            t += g_spart[(size_t)p * M_TOTAL + b * S + s];
        v[i] = t;
    }
    float mx = v[0];
#pragma unroll
    for (int i = 1; i < 8; ++i) mx = fmaxf(mx, v[i]);
    sm[tid] = mx;
    __syncthreads();
    for (int off = 128; off; off >>= 1) {
        if (tid < off) sm[tid] = fmaxf(sm[tid], sm[tid + off]);
        __syncthreads();
    }
    mx = sm[0];
    __syncthreads();
    float sum = 0.f;
#pragma unroll
    for (int i = 0; i < 8; ++i) {
        v[i] = expf(v[i] - mx);
        sum += v[i];
    }
    sm[tid] = sum;
    __syncthreads();
    for (int off = 128; off; off >>= 1) {
        if (tid < off) sm[tid] += sm[tid + off];
        __syncthreads();
    }
    float inv = 1.0f / sm[0];
#pragma unroll
    for (int i = 0; i < 8; ++i)
        wout[b * S + tid + i * 256] = v[i] * inv;
}

// ---------------------------------------------------------------------------
// K4: partial context GEMV
// ---------------------------------------------------------------------------
__global__ void k4_context(const float* __restrict__ keys,
                           const float* __restrict__ w) {
    const int b  = blockIdx.x;
    const int hc = blockIdx.y;
    const int sc = blockIdx.z;
    const int h  = hc * 128 + threadIdx.x;
    const float* kb = keys + ((size_t)b * S + sc * 512) * H + h;
    const float* wb = w + b * S + sc * 512;
    float acc = 0.f;
#pragma unroll 8
    for (int s = 0; s < 512; ++s)
        acc += wb[s] * kb[(size_t)s * H];
    g_cpart[sc * (B * H) + b * H + h] = acc;
}

// ---------------------------------------------------------------------------
// K5: reduce context partials
// ---------------------------------------------------------------------------
__global__ void k5_reduce(float* __restrict__ ctx) {
    int i = blockIdx.x * 256 + threadIdx.x;
    ctx[i] = g_cpart[i] + g_cpart[B * H + i] + g_cpart[2 * B * H + i] +
             g_cpart[3 * B * H + i];
}

// ---------------------------------------------------------------------------
// launch
// ---------------------------------------------------------------------------
extern "C" void kernel_launch(void* const* d_in, const int* in_sizes, int n_in,
                              void* d_out, int out_size) {
    const float* query = (const float*)d_in[0];
    const float* keys  = (const float*)d_in[1];
    const float* Wa_w  = (const float*)d_in[2];
    const float* Wa_b  = (const float*)d_in[3];
    const float* Ua_w  = (const float*)d_in[4];
    const float* Ua_b  = (const float*)d_in[5];
    const float* Va_w  = (const float*)d_in[6];
    // Va_b (d_in[7]) softmax-invariant; idx (d_in[8]) unused.

    float* out = (float*)d_out;
    float* ctx_out = out;             // (B,1,H)
    float* w_out   = out + B * H;     // (B,1,S)

    cudaFuncSetAttribute(k2_mma, cudaFuncAttributeMaxDynamicSharedMemorySize,
                         K2_SMEM);

    k1_qproj<<<4096, 256>>>(query, Wa_w, Wa_b, Ua_b);

    dim3 g2(8, 512);
    k2_mma<<<g2, 256, K2_SMEM>>>(keys, Ua_w, Va_w);

    k3_softmax<<<B, 256>>>(w_out);

    dim3 g4(B, H / 128, 4);
    k4_context<<<g4, 128>>>(keys, w_out);
    k5_reduce<<<(B * H) / 256, 256>>>(ctx_out);
}

// round 7
// speedup vs baseline: 2.0597x; 1.5407x over previous
#include <cuda_runtime.h>
#include <cuda_bf16.h>
#include <cuda_fp16.h>
#include <math.h>
#include <stdint.h>

typedef unsigned long long ull;

// Problem constants
#define B 32
#define S 2048
#define H 1024
#define M_TOTAL (B * S)

// ---------------------------------------------------------------------------
// Scratch (no allocations allowed -> __device__ globals)
// ---------------------------------------------------------------------------
__device__ float g_qp[B * H];            // q_proj + Wa_b + Ua_b
__device__ float g_spart[8 * M_TOTAL];   // per-n-tile partial scores
__device__ float g_cpart[4 * B * H];     // per-s-chunk partial context

// ---------------------------------------------------------------------------
// Asm helpers (base-target-safe: ldmatrix / mma.sync only)
// ---------------------------------------------------------------------------
__device__ __forceinline__ uint32_t smem_u32(const void* p) {
    uint32_t a;
    asm("{ .reg .u64 t; cvta.to.shared.u64 t, %1; cvt.u32.u64 %0, t; }"
        : "=r"(a) : "l"(p));
    return a;
}

#define STS64(smem_addr, val) \
    asm volatile("st.shared.b64 [%0], %1;" :: "r"(smem_addr), "l"(val) : "memory")

#define LDSM_X4(r, addr)                                                      \
    asm volatile("ldmatrix.sync.aligned.m8n8.x4.shared.b16 {%0,%1,%2,%3}, [%4];" \
                 : "=r"((r)[0]), "=r"((r)[1]), "=r"((r)[2]), "=r"((r)[3])     \
                 : "r"(addr))

#define LDSM_X2(r, addr)                                                      \
    asm volatile("ldmatrix.sync.aligned.m8n8.x2.shared.b16 {%0,%1}, [%2];"    \
                 : "=r"((r)[0]), "=r"((r)[1])                                 \
                 : "r"(addr))

#define MMAF16(d, a, bq)                                                      \
    asm volatile("mma.sync.aligned.m16n8k16.row.col.f32.f16.f16.f32 "         \
                 "{%0,%1,%2,%3}, {%4,%5,%6,%7}, {%8,%9}, {%0,%1,%2,%3};"      \
                 : "+f"((d)[0]), "+f"((d)[1]), "+f"((d)[2]), "+f"((d)[3])     \
                 : "r"((a)[0]), "r"((a)[1]), "r"((a)[2]), "r"((a)[3]),        \
                   "r"((bq)[0]), "r"((bq)[1]))

// convert fp32x4 -> fp16 quad (8B)
__device__ __forceinline__ ull cvt4h(float4 v) {
    __half2 h01 = __floats2half2_rn(v.x, v.y);
    __half2 h23 = __floats2half2_rn(v.z, v.w);
    return ((ull)*(uint32_t*)&h23 << 32) | *(uint32_t*)&h01;
}

// ---------------------------------------------------------------------------
// K1: q_proj[b][o] = query[b,:] . Wa_w[o,:] + Wa_b[o] + Ua_b[o]
// ---------------------------------------------------------------------------
__global__ void k1_qproj(const float* __restrict__ query,
                         const float* __restrict__ Wa_w,
                         const float* __restrict__ Wa_b,
                         const float* __restrict__ Ua_b) {
    int gw   = (blockIdx.x * blockDim.x + threadIdx.x) >> 5;
    int lane = threadIdx.x & 31;
    int b = gw >> 10;
    int o = gw & 1023;
    const float* qr = query + b * H;
    const float* wr = Wa_w + (size_t)o * H;
    float acc = 0.f;
#pragma unroll 4
    for (int i = lane; i < H; i += 32)
        acc += qr[i] * wr[i];
#pragma unroll
    for (int off = 16; off; off >>= 1)
        acc += __shfl_xor_sync(0xFFFFFFFFu, acc, off);
    if (lane == 0)
        g_qp[gw] = acc + Wa_b[o] + Ua_b[o];
}

// ---------------------------------------------------------------------------
// K2: single-term fp16 mma.sync GEMM + fused tanh/Va epilogue.
//   keys and Ua both rounded to fp16 (error budget ~1.5e-4 on weights,
//   validated against measured 7.2e-5 for the b-side-only variant).
// CTA tile 128(m) x 128(n), K chunk 64, double-buffered smem, 512 threads.
// Warp tile 32x32 (warp_m 0..3, warp_n 0..3). grid = (8 n-tiles, 512 m-tiles).
// ---------------------------------------------------------------------------
#define NC 16                      // 1024 / 64 k-chunks
#define TILE_B 16384               // 128 rows x 128B (64 fp16)
#define STAGE_B (2 * TILE_B)       // A, B
#define SM_RED (2 * STAGE_B)       // 65536: 128 x 16 floats (8KB)
#define SM_VA (SM_RED + 8192)
#define SM_QP (SM_VA + 512)
#define K2_SMEM (SM_QP + 512)      // 74752 B

__global__ __launch_bounds__(512, 1)
void k2_mma(const float* __restrict__ keys,
            const float* __restrict__ Ua_w,
            const float* __restrict__ Va_w) {
    extern __shared__ char smem[];
    const uint32_t sb = smem_u32(smem);
    const int tid = threadIdx.x;
    const int lane = tid & 31;
    const int wid = tid >> 5;
    const int warp_m = wid >> 2;          // 0..3 (32 rows each)
    const int warp_n = wid & 3;           // 0..3 (32 cols each)
    const int n0 = blockIdx.x * 128;
    const int m0 = blockIdx.y * 128;
    const int b  = blockIdx.y >> 4;       // 16 m-tiles per batch

    // epilogue constants into smem (consumed after mainloop)
    if (tid < 128) {
        ((float*)(smem + SM_VA))[tid] = Va_w[n0 + tid];
        ((float*)(smem + SM_QP))[tid] = g_qp[b * H + n0 + tid];
    }

    // loader indexing: 4 threads per row, 4 float4 each
    const int lrow = tid >> 2;            // 0..127
    const int lf4b = (tid & 3) * 4;       // 0,4,8,12
    const float* Ag = keys + (size_t)(m0 + lrow) * H;
    const float* Bg = Ua_w + (size_t)(n0 + lrow) * H;

    float acc[2][4][4];
#pragma unroll
    for (int i = 0; i < 2; ++i)
#pragma unroll
        for (int j = 0; j < 4; ++j)
#pragma unroll
            for (int k = 0; k < 4; ++k) acc[i][j][k] = 0.f;

    // ---- prologue: fill stage 0 ----
#pragma unroll
    for (int j = 0; j < 4; ++j) {
        const int f4 = lf4b + j;
        const uint32_t sw = (uint32_t)lrow * 128 +
                            ((((uint32_t)f4 >> 1) ^ (lrow & 7)) << 4) +
                            (f4 & 1) * 8;
        STS64(sb + sw, cvt4h(*(const float4*)(Ag + f4 * 4)));
        STS64(sb + TILE_B + sw, cvt4h(*(const float4*)(Bg + f4 * 4)));
    }
    __syncthreads();

    // ---- mainloop ----
    for (int c = 0; c < NC; ++c) {
        const uint32_t cur = sb + (uint32_t)(c & 1) * STAGE_B;
        const uint32_t nxt = sb + (uint32_t)((c + 1) & 1) * STAGE_B;
        const int k0n = (c + 1) * 64;

#pragma unroll
        for (int ks = 0; ks < 4; ++ks) {
            // interleave next-stage loads (1 A + 1 B float4 per quarter)
            if (c + 1 < NC) {
                const int f4 = lf4b + ks;
                const uint32_t sw = (uint32_t)lrow * 128 +
                                    ((((uint32_t)f4 >> 1) ^ (lrow & 7)) << 4) +
                                    (f4 & 1) * 8;
                STS64(nxt + sw, cvt4h(*(const float4*)(Ag + k0n + f4 * 4)));
                STS64(nxt + TILE_B + sw,
                      cvt4h(*(const float4*)(Bg + k0n + f4 * 4)));
            }

            // ldmatrix fragments
            uint32_t ah[2][4];
#pragma unroll
            for (int fm = 0; fm < 2; ++fm) {
                const int row = warp_m * 32 + fm * 16 + (lane & 15);
                const int ch = ks * 2 + (lane >> 4);
                const uint32_t ad = cur + (uint32_t)row * 128 +
                                    (((uint32_t)(ch ^ (row & 7))) << 4);
                LDSM_X4(ah[fm], ad);
            }
            uint32_t bh[4][2];
#pragma unroll
            for (int fn = 0; fn < 4; ++fn) {
                const int rn = warp_n * 32 + fn * 8 + (lane & 7);
                const int ch = ks * 2 + ((lane >> 3) & 1);
                const uint32_t bd = cur + TILE_B + (uint32_t)rn * 128 +
                                    (((uint32_t)(ch ^ (rn & 7))) << 4);
                LDSM_X2(bh[fn], bd);
            }

            // single-term MMAs
#pragma unroll
            for (int fm = 0; fm < 2; ++fm) {
#pragma unroll
                for (int fn = 0; fn < 4; ++fn) {
                    MMAF16(acc[fm][fn], ah[fm], bh[fn]);
                }
            }
        }
        __syncthreads();
    }

    // ---- fused epilogue: tanh + Va dot, reduce over columns ----
    const float* sva = (const float*)(smem + SM_VA);
    const float* sqp = (const float*)(smem + SM_QP);
    float* red = (float*)(smem + SM_RED);
    const int quad = lane & 3;
    const int ln4 = lane >> 2;
    const int slot = warp_n * 4 + quad;

#pragma unroll
    for (int fm = 0; fm < 2; ++fm) {
        float rv0 = 0.f, rv1 = 0.f;
#pragma unroll
        for (int fn = 0; fn < 4; ++fn) {
            const int c0 = warp_n * 32 + fn * 8 + quad * 2;
            const int c1 = c0 + 1;
            rv0 += sva[c0] * tanhf(acc[fm][fn][0] + sqp[c0]);
            rv0 += sva[c1] * tanhf(acc[fm][fn][1] + sqp[c1]);
            rv1 += sva[c0] * tanhf(acc[fm][fn][2] + sqp[c0]);
            rv1 += sva[c1] * tanhf(acc[fm][fn][3] + sqp[c1]);
        }
        const int rowA = warp_m * 32 + fm * 16 + ln4;
        red[rowA * 16 + slot] = rv0;
        red[(rowA + 8) * 16 + slot] = rv1;
    }
    __syncthreads();
    if (tid < 128) {
        float s = 0.f;
#pragma unroll
        for (int t = 0; t < 16; ++t) s += red[tid * 16 + t];
        g_spart[(size_t)blockIdx.x * M_TOTAL + m0 + tid] = s;
    }
}

// ---------------------------------------------------------------------------
// K3: reduce 8 partials per row + softmax -> weights
// ---------------------------------------------------------------------------
__global__ void k3_softmax(float* __restrict__ wout) {
    __shared__ float sm[256];
    const int b = blockIdx.x;
    const int tid = threadIdx.x;

    float v[8];
#pragma unroll
    for (int i = 0; i < 8; ++i) {
        int s = tid + i * 256;
        float t = 0.f;
#pragma unroll
        for (int p = 0; p < 8; ++p)
            t += g_spart[(size_t)p * M_TOTAL + b * S + s];
        v[i] = t;
    }
    float mx = v[0];
#pragma unroll
    for (int i = 1; i < 8; ++i) mx = fmaxf(mx, v[i]);
    sm[tid] = mx;
    __syncthreads();
    for (int off = 128; off; off >>= 1) {
        if (tid < off) sm[tid] = fmaxf(sm[tid], sm[tid + off]);
        __syncthreads();
    }
    mx = sm[0];
    __syncthreads();
    float sum = 0.f;
#pragma unroll
    for (int i = 0; i < 8; ++i) {
        v[i] = expf(v[i] - mx);
        sum += v[i];
    }
    sm[tid] = sum;
    __syncthreads();
    for (int off = 128; off; off >>= 1) {
        if (tid < off) sm[tid] += sm[tid + off];
        __syncthreads();
    }
    float inv = 1.0f / sm[0];
#pragma unroll
    for (int i = 0; i < 8; ++i)
        wout[b * S + tid + i * 256] = v[i] * inv;
}

// ---------------------------------------------------------------------------
// K4: partial context GEMV
// ---------------------------------------------------------------------------
__global__ void k4_context(const float* __restrict__ keys,
                           const float* __restrict__ w) {
    const int b  = blockIdx.x;
    const int hc = blockIdx.y;
    const int sc = blockIdx.z;
    const int h  = hc * 128 + threadIdx.x;
    const float* kb = keys + ((size_t)b * S + sc * 512) * H + h;
    const float* wb = w + b * S + sc * 512;
    float acc = 0.f;
#pragma unroll 8
    for (int s = 0; s < 512; ++s)
        acc += wb[s] * kb[(size_t)s * H];
    g_cpart[sc * (B * H) + b * H + h] = acc;
}

// ---------------------------------------------------------------------------
// K5: reduce context partials
// ---------------------------------------------------------------------------
__global__ void k5_reduce(float* __restrict__ ctx) {
    int i = blockIdx.x * 256 + threadIdx.x;
    ctx[i] = g_cpart[i] + g_cpart[B * H + i] + g_cpart[2 * B * H + i] +
             g_cpart[3 * B * H + i];
}

// ---------------------------------------------------------------------------
// launch
// ---------------------------------------------------------------------------
extern "C" void kernel_launch(void* const* d_in, const int* in_sizes, int n_in,
                              void* d_out, int out_size) {
    const float* query = (const float*)d_in[0];
    const float* keys  = (const float*)d_in[1];
    const float* Wa_w  = (const float*)d_in[2];
    const float* Wa_b  = (const float*)d_in[3];
    const float* Ua_w  = (const float*)d_in[4];
    const float* Ua_b  = (const float*)d_in[5];
    const float* Va_w  = (const float*)d_in[6];
    // Va_b (d_in[7]) softmax-invariant; idx (d_in[8]) unused.

    float* out = (float*)d_out;
    float* ctx_out = out;             // (B,1,H)
    float* w_out   = out + B * H;     // (B,1,S)

    cudaFuncSetAttribute(k2_mma, cudaFuncAttributeMaxDynamicSharedMemorySize,
                         K2_SMEM);

    k1_qproj<<<4096, 256>>>(query, Wa_w, Wa_b, Ua_b);

    dim3 g2(8, 512);
    k2_mma<<<g2, 512, K2_SMEM>>>(keys, Ua_w, Va_w);

    k3_softmax<<<B, 256>>>(w_out);

    dim3 g4(B, H / 128, 4);
    k4_context<<<g4, 128>>>(keys, w_out);
    k5_reduce<<<(B * H) / 256, 256>>>(ctx_out);
}

// round 9
// speedup vs baseline: 4.1340x; 2.0071x over previous
#include <cuda_runtime.h>
#include <cuda_bf16.h>
#include <cuda_fp16.h>
#include <math.h>
#include <stdint.h>

typedef unsigned long long ull;

// Problem constants
#define B 32
#define S 2048
#define H 1024
#define M_TOTAL (B * S)
#define KEY_GROUPS (B * S * H / 8)     // 8-elem conversion groups for keys
#define UA_GROUPS (H * H / 8)

// ---------------------------------------------------------------------------
// Scratch (no allocations allowed -> __device__ globals)
// ---------------------------------------------------------------------------
__device__ float g_qp[B * H];            // q_proj + Wa_b + Ua_b
__device__ float g_spart[8 * M_TOTAL];   // per-n-tile partial scores
__device__ float g_cpart[4 * B * H];     // per-s-chunk partial context
__device__ __half g_keys_h[(size_t)B * S * H];   // fp16 keys (128 MB)
__device__ __half g_ua_h[H * H];                 // fp16 Ua (2 MB)

// ---------------------------------------------------------------------------
// Asm helpers (base-target-safe: ldmatrix / mma.sync / cp.async, sm_80+)
// ---------------------------------------------------------------------------
__device__ __forceinline__ uint32_t smem_u32(const void* p) {
    uint32_t a;
    asm("{ .reg .u64 t; cvta.to.shared.u64 t, %1; cvt.u32.u64 %0, t; }"
        : "=r"(a) : "l"(p));
    return a;
}

__device__ __forceinline__ void cpa16(uint32_t dst, const void* src) {
    asm volatile("cp.async.cg.shared.global [%0], [%1], 16;"
                 :: "r"(dst), "l"(src) : "memory");
}
#define CP_COMMIT() asm volatile("cp.async.commit_group;" ::: "memory")
#define CP_WAIT1()  asm volatile("cp.async.wait_group 1;" ::: "memory")

#define LDSM_X4(r, addr)                                                      \
    asm volatile("ldmatrix.sync.aligned.m8n8.x4.shared.b16 {%0,%1,%2,%3}, [%4];" \
                 : "=r"((r)[0]), "=r"((r)[1]), "=r"((r)[2]), "=r"((r)[3])     \
                 : "r"(addr))

#define LDSM_X2(r, addr)                                                      \
    asm volatile("ldmatrix.sync.aligned.m8n8.x2.shared.b16 {%0,%1}, [%2];"    \
                 : "=r"((r)[0]), "=r"((r)[1])                                 \
                 : "r"(addr))

#define MMAF16(d, a, bq)                                                      \
    asm volatile("mma.sync.aligned.m16n8k16.row.col.f32.f16.f16.f32 "         \
                 "{%0,%1,%2,%3}, {%4,%5,%6,%7}, {%8,%9}, {%0,%1,%2,%3};"      \
                 : "+f"((d)[0]), "+f"((d)[1]), "+f"((d)[2]), "+f"((d)[3])     \
                 : "r"((a)[0]), "r"((a)[1]), "r"((a)[2]), "r"((a)[3]),        \
                   "r"((bq)[0]), "r"((bq)[1]))

// ---------------------------------------------------------------------------
// K0: fp32 -> fp16 prepass for keys and Ua_w (8 elems / thread, 16B stores)
// ---------------------------------------------------------------------------
__global__ void k0_cvt(const float* __restrict__ keys,
                       const float* __restrict__ ua) {
    size_t g = (size_t)blockIdx.x * blockDim.x + threadIdx.x;
    const float* src;
    __half* dst;
    size_t idx;
    if (g < KEY_GROUPS) {
        src = keys; dst = g_keys_h; idx = g;
    } else {
        src = ua; dst = g_ua_h; idx = g - KEY_GROUPS;
    }
    float4 a = ((const float4*)src)[idx * 2];
    float4 b = ((const float4*)src)[idx * 2 + 1];
    __half2 h0 = __floats2half2_rn(a.x, a.y);
    __half2 h1 = __floats2half2_rn(a.z, a.w);
    __half2 h2 = __floats2half2_rn(b.x, b.y);
    __half2 h3 = __floats2half2_rn(b.z, b.w);
    uint4 out;
    out.x = *(uint32_t*)&h0;
    out.y = *(uint32_t*)&h1;
    out.z = *(uint32_t*)&h2;
    out.w = *(uint32_t*)&h3;
    ((uint4*)dst)[idx] = out;
}

// ---------------------------------------------------------------------------
// K1: q_proj[b][o] = query[b,:] . Wa_w[o,:] + Wa_b[o] + Ua_b[o]
// ---------------------------------------------------------------------------
__global__ void k1_qproj(const float* __restrict__ query,
                         const float* __restrict__ Wa_w,
                         const float* __restrict__ Wa_b,
                         const float* __restrict__ Ua_b) {
    int gw   = (blockIdx.x * blockDim.x + threadIdx.x) >> 5;
    int lane = threadIdx.x & 31;
    int b = gw >> 10;
    int o = gw & 1023;
    const float* qr = query + b * H;
    const float* wr = Wa_w + (size_t)o * H;
    float acc = 0.f;
#pragma unroll 4
    for (int i = lane; i < H; i += 32)
        acc += qr[i] * wr[i];
#pragma unroll
    for (int off = 16; off; off >>= 1)
        acc += __shfl_xor_sync(0xFFFFFFFFu, acc, off);
    if (lane == 0)
        g_qp[gw] = acc + Wa_b[o] + Ua_b[o];
}

// ---------------------------------------------------------------------------
// K2: single-term fp16 mma.sync GEMM, cp.async 3-stage pipeline,
//     fused tanh/Va epilogue. CTA 128x128, K chunk 64, 512 threads,
//     warp tile 32x32. grid = (8 n-tiles, 512 m-tiles).
// ---------------------------------------------------------------------------
#define NC 16                      // 1024 / 64 k-chunks
#define TILE_B 16384               // 128 rows x 128B (64 fp16)
#define STAGE_B (2 * TILE_B)       // A, B  (32 KB)
#define NSTAGE 3
#define SM_RED (NSTAGE * STAGE_B)  // 98304: 128 x 16 floats (8KB)
#define SM_VA (SM_RED + 8192)
#define SM_QP (SM_VA + 512)
#define K2_SMEM (SM_QP + 512)      // 107520 B

__global__ __launch_bounds__(512, 1)
void k2_mma(const float* __restrict__ Va_w) {
    extern __shared__ char smem[];
    const uint32_t sb = smem_u32(smem);
    const int tid = threadIdx.x;
    const int lane = tid & 31;
    const int wid = tid >> 5;
    const int warp_m = wid >> 2;          // 0..3 (32 rows each)
    const int warp_n = wid & 3;           // 0..3 (32 cols each)
    const int n0 = blockIdx.x * 128;
    const int m0 = blockIdx.y * 128;
    const int b  = blockIdx.y >> 4;       // 16 m-tiles per batch

    // epilogue constants into smem (consumed after mainloop)
    if (tid < 128) {
        ((float*)(smem + SM_VA))[tid] = Va_w[n0 + tid];
        ((float*)(smem + SM_QP))[tid] = g_qp[b * H + n0 + tid];
    }

    // loader indexing: 4 threads per row, 2 granules (16B = 8 fp16) each
    const int lrow = tid >> 2;            // 0..127
    const int g0 = (tid & 3) * 2;         // 0,2,4,6
    const __half* Ag = g_keys_h + (size_t)(m0 + lrow) * H;
    const __half* Bg = g_ua_h + (size_t)(n0 + lrow) * H;
    const uint32_t sw0 = (uint32_t)lrow * 128 +
                         (((uint32_t)(g0 + 0) ^ (lrow & 7)) << 4);
    const uint32_t sw1 = (uint32_t)lrow * 128 +
                         (((uint32_t)(g0 + 1) ^ (lrow & 7)) << 4);

    float acc[2][4][4];
#pragma unroll
    for (int i = 0; i < 2; ++i)
#pragma unroll
        for (int j = 0; j < 4; ++j)
#pragma unroll
            for (int k = 0; k < 4; ++k) acc[i][j][k] = 0.f;

    // ---- prologue: issue stages 0 and 1 ----
#pragma unroll
    for (int s = 0; s < 2; ++s) {
        const uint32_t st = sb + s * STAGE_B;
        const int k0 = s * 64;
        cpa16(st + sw0, Ag + k0 + (g0 + 0) * 8);
        cpa16(st + sw1, Ag + k0 + (g0 + 1) * 8);
        cpa16(st + TILE_B + sw0, Bg + k0 + (g0 + 0) * 8);
        cpa16(st + TILE_B + sw1, Bg + k0 + (g0 + 1) * 8);
        CP_COMMIT();
    }

    // ---- mainloop ----
    int stage_c = 0;   // stage index of chunk c
    for (int c = 0; c < NC; ++c) {
        CP_WAIT1();                 // stage c landed (pending <= 1)
        __syncthreads();            // all warps done with stage c-1 reads

        // issue chunk c+2 into stage (c+2)%NSTAGE (== (c-1)%NSTAGE, now free)
        if (c + 2 < NC) {
            int sn = stage_c + 2;
            if (sn >= NSTAGE) sn -= NSTAGE;
            const uint32_t st = sb + sn * STAGE_B;
            const int k0 = (c + 2) * 64;
            cpa16(st + sw0, Ag + k0 + (g0 + 0) * 8);
            cpa16(st + sw1, Ag + k0 + (g0 + 1) * 8);
            cpa16(st + TILE_B + sw0, Bg + k0 + (g0 + 0) * 8);
            cpa16(st + TILE_B + sw1, Bg + k0 + (g0 + 1) * 8);
        }
        CP_COMMIT();                // commit (possibly empty) keeps count fixed

        const uint32_t cur = sb + stage_c * STAGE_B;
#pragma unroll
        for (int ks = 0; ks < 4; ++ks) {
            uint32_t ah[2][4];
#pragma unroll
            for (int fm = 0; fm < 2; ++fm) {
                const int row = warp_m * 32 + fm * 16 + (lane & 15);
                const int ch = ks * 2 + (lane >> 4);
                const uint32_t ad = cur + (uint32_t)row * 128 +
                                    (((uint32_t)(ch ^ (row & 7))) << 4);
                LDSM_X4(ah[fm], ad);
            }
            uint32_t bh[4][2];
#pragma unroll
            for (int fn = 0; fn < 4; ++fn) {
                const int rn = warp_n * 32 + fn * 8 + (lane & 7);
                const int ch = ks * 2 + ((lane >> 3) & 1);
                const uint32_t bd = cur + TILE_B + (uint32_t)rn * 128 +
                                    (((uint32_t)(ch ^ (rn & 7))) << 4);
                LDSM_X2(bh[fn], bd);
            }
#pragma unroll
            for (int fm = 0; fm < 2; ++fm) {
#pragma unroll
                for (int fn = 0; fn < 4; ++fn) {
                    MMAF16(acc[fm][fn], ah[fm], bh[fn]);
                }
            }
        }
        stage_c = (stage_c + 1 == NSTAGE) ? 0 : stage_c + 1;
    }

    // ---- fused epilogue: tanh + Va dot, reduce over columns ----
    const float* sva = (const float*)(smem + SM_VA);
    const float* sqp = (const float*)(smem + SM_QP);
    float* red = (float*)(smem + SM_RED);
    const int quad = lane & 3;
    const int ln4 = lane >> 2;
    const int slot = warp_n * 4 + quad;

    __syncthreads();   // mainloop reads finished before red[] overwrites smem

#pragma unroll
    for (int fm = 0; fm < 2; ++fm) {
        float rv0 = 0.f, rv1 = 0.f;
#pragma unroll
        for (int fn = 0; fn < 4; ++fn) {
            const int c0 = warp_n * 32 + fn * 8 + quad * 2;
            const int c1 = c0 + 1;
            rv0 += sva[c0] * tanhf(acc[fm][fn][0] + sqp[c0]);
            rv0 += sva[c1] * tanhf(acc[fm][fn][1] + sqp[c1]);
            rv1 += sva[c0] * tanhf(acc[fm][fn][2] + sqp[c0]);
            rv1 += sva[c1] * tanhf(acc[fm][fn][3] + sqp[c1]);
        }
        const int rowA = warp_m * 32 + fm * 16 + ln4;
        red[rowA * 16 + slot] = rv0;
        red[(rowA + 8) * 16 + slot] = rv1;
    }
    __syncthreads();
    if (tid < 128) {
        float s = 0.f;
#pragma unroll
        for (int t = 0; t < 16; ++t) s += red[tid * 16 + t];
        g_spart[(size_t)blockIdx.x * M_TOTAL + m0 + tid] = s;
    }
}

// ---------------------------------------------------------------------------
// K3: reduce 8 partials per row + softmax -> weights
// ---------------------------------------------------------------------------
__global__ void k3_softmax(float* __restrict__ wout) {
    __shared__ float sm[256];
    const int b = blockIdx.x;
    const int tid = threadIdx.x;

    float v[8];
#pragma unroll
    for (int i = 0; i < 8; ++i) {
        int s = tid + i * 256;
        float t = 0.f;
#pragma unroll
        for (int p = 0; p < 8; ++p)
            t += g_spart[(size_t)p * M_TOTAL + b * S + s];
        v[i] = t;
    }
    float mx = v[0];
#pragma unroll
    for (int i = 1; i < 8; ++i) mx = fmaxf(mx, v[i]);
    sm[tid] = mx;
    __syncthreads();
    for (int off = 128; off; off >>= 1) {
        if (tid < off) sm[tid] = fmaxf(sm[tid], sm[tid + off]);
        __syncthreads();
    }
    mx = sm[0];
    __syncthreads();
    float sum = 0.f;
#pragma unroll
    for (int i = 0; i < 8; ++i) {
        v[i] = expf(v[i] - mx);
        sum += v[i];
    }
    sm[tid] = sum;
    __syncthreads();
    for (int off = 128; off; off >>= 1) {
        if (tid < off) sm[tid] += sm[tid + off];
        __syncthreads();
    }
    float inv = 1.0f / sm[0];
#pragma unroll
    for (int i = 0; i < 8; ++i)
        wout[b * S + tid + i * 256] = v[i] * inv;
}

// ---------------------------------------------------------------------------
// K4: partial context GEMV (fp32 keys for full precision)
// ---------------------------------------------------------------------------
__global__ void k4_context(const float* __restrict__ keys,
                           const float* __restrict__ w) {
    const int b  = blockIdx.x;
    const int hc = blockIdx.y;
    const int sc = blockIdx.z;
    const int h  = hc * 128 + threadIdx.x;
    const float* kb = keys + ((size_t)b * S + sc * 512) * H + h;
    const float* wb = w + b * S + sc * 512;
    float acc = 0.f;
#pragma unroll 8
    for (int s = 0; s < 512; ++s)
        acc += wb[s] * kb[(size_t)s * H];
    g_cpart[sc * (B * H) + b * H + h] = acc;
}

// ---------------------------------------------------------------------------
// K5: reduce context partials
// ---------------------------------------------------------------------------
__global__ void k5_reduce(float* __restrict__ ctx) {
    int i = blockIdx.x * 256 + threadIdx.x;
    ctx[i] = g_cpart[i] + g_cpart[B * H + i] + g_cpart[2 * B * H + i] +
             g_cpart[3 * B * H + i];
}

// ---------------------------------------------------------------------------
// launch
// ---------------------------------------------------------------------------
extern "C" void kernel_launch(void* const* d_in, const int* in_sizes, int n_in,
                              void* d_out, int out_size) {
    const float* query = (const float*)d_in[0];
    const float* keys  = (const float*)d_in[1];
    const float* Wa_w  = (const float*)d_in[2];
    const float* Wa_b  = (const float*)d_in[3];
    const float* Ua_w  = (const float*)d_in[4];
    const float* Ua_b  = (const float*)d_in[5];
    const float* Va_w  = (const float*)d_in[6];
    // Va_b (d_in[7]) softmax-invariant; idx (d_in[8]) unused.

    float* out = (float*)d_out;
    float* ctx_out = out;             // (B,1,H)
    float* w_out   = out + B * H;     // (B,1,S)

    cudaFuncSetAttribute(k2_mma, cudaFuncAttributeMaxDynamicSharedMemorySize,
                         K2_SMEM);

    // K0: fp32 -> fp16 prepass (keys + Ua)
    k0_cvt<<<(KEY_GROUPS + UA_GROUPS) / 256, 256>>>(keys, Ua_w);

    k1_qproj<<<4096, 256>>>(query, Wa_w, Wa_b, Ua_b);

    dim3 g2(8, 512);
    k2_mma<<<g2, 512, K2_SMEM>>>(Va_w);

    k3_softmax<<<B, 256>>>(w_out);

    dim3 g4(B, H / 128, 4);
    k4_context<<<g4, 128>>>(keys, w_out);
    k5_reduce<<<(B * H) / 256, 256>>>(ctx_out);
}

// round 10
// speedup vs baseline: 4.3466x; 1.0514x over previous
#include <cuda_runtime.h>
#include <cuda_bf16.h>
#include <cuda_fp16.h>
#include <math.h>
#include <stdint.h>

typedef unsigned long long ull;

// Problem constants
#define B 32
#define S 2048
#define H 1024
#define M_TOTAL (B * S)
#define KEY_GROUPS (B * S * H / 8)     // 8-elem conversion groups for keys
#define UA_GROUPS (H * H / 8)

// ---------------------------------------------------------------------------
// Scratch (no allocations allowed -> __device__ globals)
// ---------------------------------------------------------------------------
__device__ float g_qp[B * H];            // q_proj + Wa_b + Ua_b
__device__ float g_spart[8 * M_TOTAL];   // per-n-tile partial scores
__device__ float g_cpart[4 * B * H];     // per-s-chunk partial context
__device__ __half g_keys_h[(size_t)B * S * H];   // fp16 keys (128 MB)
__device__ __half g_ua_h[H * H];                 // fp16 Ua (2 MB)

// ---------------------------------------------------------------------------
// Asm helpers (base-target-safe: ldmatrix / mma.sync / cp.async, sm_80+)
// ---------------------------------------------------------------------------
__device__ __forceinline__ uint32_t smem_u32(const void* p) {
    uint32_t a;
    asm("{ .reg .u64 t; cvta.to.shared.u64 t, %1; cvt.u32.u64 %0, t; }"
        : "=r"(a) : "l"(p));
    return a;
}

__device__ __forceinline__ void cpa16(uint32_t dst, const void* src) {
    asm volatile("cp.async.cg.shared.global [%0], [%1], 16;"
                 :: "r"(dst), "l"(src) : "memory");
}
#define CP_COMMIT() asm volatile("cp.async.commit_group;" ::: "memory")
#define CP_WAIT1()  asm volatile("cp.async.wait_group 1;" ::: "memory")

#define LDSM_X4(r, addr)                                                      \
    asm volatile("ldmatrix.sync.aligned.m8n8.x4.shared.b16 {%0,%1,%2,%3}, [%4];" \
                 : "=r"((r)[0]), "=r"((r)[1]), "=r"((r)[2]), "=r"((r)[3])     \
                 : "r"(addr))

#define MMAF16(d, a, bq)                                                      \
    asm volatile("mma.sync.aligned.m16n8k16.row.col.f32.f16.f16.f32 "         \
                 "{%0,%1,%2,%3}, {%4,%5,%6,%7}, {%8,%9}, {%0,%1,%2,%3};"      \
                 : "+f"((d)[0]), "+f"((d)[1]), "+f"((d)[2]), "+f"((d)[3])     \
                 : "r"((a)[0]), "r"((a)[1]), "r"((a)[2]), "r"((a)[3]),        \
                   "r"((bq)[0]), "r"((bq)[1]))

// ---------------------------------------------------------------------------
// K0: fp32 -> fp16 prepass for keys and Ua_w (8 elems / thread, 16B stores)
// ---------------------------------------------------------------------------
__global__ void k0_cvt(const float* __restrict__ keys,
                       const float* __restrict__ ua) {
    size_t g = (size_t)blockIdx.x * blockDim.x + threadIdx.x;
    const float* src;
    __half* dst;
    size_t idx;
    if (g < KEY_GROUPS) {
        src = keys; dst = g_keys_h; idx = g;
    } else {
        src = ua; dst = g_ua_h; idx = g - KEY_GROUPS;
    }
    float4 a = ((const float4*)src)[idx * 2];
    float4 b = ((const float4*)src)[idx * 2 + 1];
    __half2 h0 = __floats2half2_rn(a.x, a.y);
    __half2 h1 = __floats2half2_rn(a.z, a.w);
    __half2 h2 = __floats2half2_rn(b.x, b.y);
    __half2 h3 = __floats2half2_rn(b.z, b.w);
    uint4 out;
    out.x = *(uint32_t*)&h0;
    out.y = *(uint32_t*)&h1;
    out.z = *(uint32_t*)&h2;
    out.w = *(uint32_t*)&h3;
    ((uint4*)dst)[idx] = out;
}

// ---------------------------------------------------------------------------
// K1: q_proj[b][o] = query[b,:] . Wa_w[o,:] + Wa_b[o] + Ua_b[o]
// ---------------------------------------------------------------------------
__global__ void k1_qproj(const float* __restrict__ query,
                         const float* __restrict__ Wa_w,
                         const float* __restrict__ Wa_b,
                         const float* __restrict__ Ua_b) {
    int gw   = (blockIdx.x * blockDim.x + threadIdx.x) >> 5;
    int lane = threadIdx.x & 31;
    int b = gw >> 10;
    int o = gw & 1023;
    const float* qr = query + b * H;
    const float* wr = Wa_w + (size_t)o * H;
    float acc = 0.f;
#pragma unroll 4
    for (int i = lane; i < H; i += 32)
        acc += qr[i] * wr[i];
#pragma unroll
    for (int off = 16; off; off >>= 1)
        acc += __shfl_xor_sync(0xFFFFFFFFu, acc, off);
    if (lane == 0)
        g_qp[gw] = acc + Wa_b[o] + Ua_b[o];
}

// ---------------------------------------------------------------------------
// K2: single-term fp16 mma.sync GEMM, cp.async 3-stage pipeline,
//     fused tanh/Va epilogue. CTA 128x128, K chunk 64, 256 threads,
//     8 warps, warp tile 64x32, 2 CTAs/SM. grid = (8 n-tiles, 512 m-tiles).
// ---------------------------------------------------------------------------
#define NC 16                      // 1024 / 64 k-chunks
#define TILE_B 16384               // 128 rows x 128B (64 fp16)
#define STAGE_B (2 * TILE_B)       // A, B  (32 KB)
#define NSTAGE 3
#define SM_RED (NSTAGE * STAGE_B)  // 98304: 128 x 16 floats (8KB)
#define SM_VA (SM_RED + 8192)
#define SM_QP (SM_VA + 512)
#define K2_SMEM (SM_QP + 512)      // 107520 B

__global__ __launch_bounds__(256, 2)
void k2_mma(const float* __restrict__ Va_w) {
    extern __shared__ char smem[];
    const uint32_t sb = smem_u32(smem);
    const int tid = threadIdx.x;
    const int lane = tid & 31;
    const int wid = tid >> 5;
    const int warp_m = wid >> 2;          // 0..1 (64 rows each)
    const int warp_n = wid & 3;           // 0..3 (32 cols each)
    const int n0 = blockIdx.x * 128;
    const int m0 = blockIdx.y * 128;
    const int b  = blockIdx.y >> 4;       // 16 m-tiles per batch

    // epilogue constants into smem (consumed after mainloop)
    if (tid < 128) {
        ((float*)(smem + SM_VA))[tid] = Va_w[n0 + tid];
        ((float*)(smem + SM_QP))[tid] = g_qp[b * H + n0 + tid];
    }

    // loader indexing: 2 threads per row, 4 granules (16B = 8 fp16) each
    const int lrow = tid >> 1;            // 0..127
    const int g0 = (tid & 1) * 4;         // 0 or 4
    const __half* Ag = g_keys_h + (size_t)(m0 + lrow) * H;
    const __half* Bg = g_ua_h + (size_t)(n0 + lrow) * H;
    uint32_t sw[4];
#pragma unroll
    for (int j = 0; j < 4; ++j)
        sw[j] = (uint32_t)lrow * 128 + (((uint32_t)(g0 + j) ^ (lrow & 7)) << 4);

    float acc[4][4][4];
#pragma unroll
    for (int i = 0; i < 4; ++i)
#pragma unroll
        for (int j = 0; j < 4; ++j)
#pragma unroll
            for (int k = 0; k < 4; ++k) acc[i][j][k] = 0.f;

    // ---- prologue: issue stages 0 and 1 ----
#pragma unroll
    for (int s = 0; s < 2; ++s) {
        const uint32_t st = sb + s * STAGE_B;
        const int k0 = s * 64;
#pragma unroll
        for (int j = 0; j < 4; ++j) {
            cpa16(st + sw[j], Ag + k0 + (g0 + j) * 8);
            cpa16(st + TILE_B + sw[j], Bg + k0 + (g0 + j) * 8);
        }
        CP_COMMIT();
    }

    // ---- mainloop ----
    int stage_c = 0;   // stage index of chunk c
    for (int c = 0; c < NC; ++c) {
        CP_WAIT1();                 // stage c landed (pending <= 1)
        __syncthreads();            // all warps done with stage c-1 reads

        // issue chunk c+2 into the stage just freed
        if (c + 2 < NC) {
            int sn = stage_c + 2;
            if (sn >= NSTAGE) sn -= NSTAGE;
            const uint32_t st = sb + sn * STAGE_B;
            const int k0 = (c + 2) * 64;
#pragma unroll
            for (int j = 0; j < 4; ++j) {
                cpa16(st + sw[j], Ag + k0 + (g0 + j) * 8);
                cpa16(st + TILE_B + sw[j], Bg + k0 + (g0 + j) * 8);
            }
        }
        CP_COMMIT();                // commit (possibly empty) keeps count fixed

        const uint32_t cur = sb + stage_c * STAGE_B;
#pragma unroll
        for (int ks = 0; ks < 4; ++ks) {
            // A fragments: 4 x LDSM_X4 (64 rows x k16)
            uint32_t ah[4][4];
#pragma unroll
            for (int fm = 0; fm < 4; ++fm) {
                const int row = warp_m * 64 + fm * 16 + (lane & 15);
                const int ch = ks * 2 + (lane >> 4);
                const uint32_t ad = cur + (uint32_t)row * 128 +
                                    (((uint32_t)(ch ^ (row & 7))) << 4);
                LDSM_X4(ah[fm], ad);
            }
            // B fragments: 2 x LDSM_X4, each covering two n8 blocks
            uint32_t bh[4][2];
#pragma unroll
            for (int fn2 = 0; fn2 < 2; ++fn2) {
                const int fn_loc = fn2 * 2 + (lane >> 4);         // n8 block
                const int kh = (lane >> 3) & 1;                    // k half
                const int rn = warp_n * 32 + fn_loc * 8 + (lane & 7);
                const int ch = ks * 2 + kh;
                const uint32_t bd = cur + TILE_B + (uint32_t)rn * 128 +
                                    (((uint32_t)(ch ^ (rn & 7))) << 4);
                uint32_t r[4];
                LDSM_X4(r, bd);
                bh[fn2 * 2 + 0][0] = r[0];
                bh[fn2 * 2 + 0][1] = r[1];
                bh[fn2 * 2 + 1][0] = r[2];
                bh[fn2 * 2 + 1][1] = r[3];
            }
#pragma unroll
            for (int fm = 0; fm < 4; ++fm) {
#pragma unroll
                for (int fn = 0; fn < 4; ++fn) {
                    MMAF16(acc[fm][fn], ah[fm], bh[fn]);
                }
            }
        }
        stage_c = (stage_c + 1 == NSTAGE) ? 0 : stage_c + 1;
    }

    // ---- fused epilogue: tanh + Va dot, reduce over columns ----
    const float* sva = (const float*)(smem + SM_VA);
    const float* sqp = (const float*)(smem + SM_QP);
    float* red = (float*)(smem + SM_RED);
    const int quad = lane & 3;
    const int ln4 = lane >> 2;
    const int slot = warp_n * 4 + quad;

    __syncthreads();   // mainloop reads finished

#pragma unroll
    for (int fm = 0; fm < 4; ++fm) {
        float rv0 = 0.f, rv1 = 0.f;
#pragma unroll
        for (int fn = 0; fn < 4; ++fn) {
            const int c0 = warp_n * 32 + fn * 8 + quad * 2;
            const int c1 = c0 + 1;
            rv0 += sva[c0] * tanhf(acc[fm][fn][0] + sqp[c0]);
            rv0 += sva[c1] * tanhf(acc[fm][fn][1] + sqp[c1]);
            rv1 += sva[c0] * tanhf(acc[fm][fn][2] + sqp[c0]);
            rv1 += sva[c1] * tanhf(acc[fm][fn][3] + sqp[c1]);
        }
        const int rowA = warp_m * 64 + fm * 16 + ln4;
        red[rowA * 16 + slot] = rv0;
        red[(rowA + 8) * 16 + slot] = rv1;
    }
    __syncthreads();
    if (tid < 128) {
        float s = 0.f;
#pragma unroll
        for (int t = 0; t < 16; ++t) s += red[tid * 16 + t];
        g_spart[(size_t)blockIdx.x * M_TOTAL + m0 + tid] = s;
    }
}

// ---------------------------------------------------------------------------
// K3: reduce 8 partials per row + softmax -> weights
// ---------------------------------------------------------------------------
__global__ void k3_softmax(float* __restrict__ wout) {
    __shared__ float sm[256];
    const int b = blockIdx.x;
    const int tid = threadIdx.x;

    float v[8];
#pragma unroll
    for (int i = 0; i < 8; ++i) {
        int s = tid + i * 256;
        float t = 0.f;
#pragma unroll
        for (int p = 0; p < 8; ++p)
            t += g_spart[(size_t)p * M_TOTAL + b * S + s];
        v[i] = t;
    }
    float mx = v[0];
#pragma unroll
    for (int i = 1; i < 8; ++i) mx = fmaxf(mx, v[i]);
    sm[tid] = mx;
    __syncthreads();
    for (int off = 128; off; off >>= 1) {
        if (tid < off) sm[tid] = fmaxf(sm[tid], sm[tid + off]);
        __syncthreads();
    }
    mx = sm[0];
    __syncthreads();
    float sum = 0.f;
#pragma unroll
    for (int i = 0; i < 8; ++i) {
        v[i] = expf(v[i] - mx);
        sum += v[i];
    }
    sm[tid] = sum;
    __syncthreads();
    for (int off = 128; off; off >>= 1) {
        if (tid < off) sm[tid] += sm[tid + off];
        __syncthreads();
    }
    float inv = 1.0f / sm[0];
#pragma unroll
    for (int i = 0; i < 8; ++i)
        wout[b * S + tid + i * 256] = v[i] * inv;
}

// ---------------------------------------------------------------------------
// K4: partial context GEMV on fp16 keys (half traffic), 2 h-cols per thread
// grid (B, H/256, 4 s-chunks), 128 threads.
// ---------------------------------------------------------------------------
__global__ void k4_context(const float* __restrict__ w) {
    const int b  = blockIdx.x;
    const int hc = blockIdx.y;
    const int sc = blockIdx.z;
    const int h2 = hc * 128 + threadIdx.x;          // half2 column index
    const __half2* kb = (const __half2*)(g_keys_h +
                        ((size_t)b * S + sc * 512) * H) + h2;
    const float* wb = w + b * S + sc * 512;
    float a0 = 0.f, a1 = 0.f;
#pragma unroll 8
    for (int s = 0; s < 512; ++s) {
        float2 kv = __half22float2(kb[(size_t)s * (H / 2)]);
        float ws = wb[s];
        a0 += ws * kv.x;
        a1 += ws * kv.y;
    }
    float* dst = g_cpart + sc * (B * H) + b * H + h2 * 2;
    dst[0] = a0;
    dst[1] = a1;
}

// ---------------------------------------------------------------------------
// K5: reduce context partials
// ---------------------------------------------------------------------------
__global__ void k5_reduce(float* __restrict__ ctx) {
    int i = blockIdx.x * 256 + threadIdx.x;
    ctx[i] = g_cpart[i] + g_cpart[B * H + i] + g_cpart[2 * B * H + i] +
             g_cpart[3 * B * H + i];
}

// ---------------------------------------------------------------------------
// launch
// ---------------------------------------------------------------------------
extern "C" void kernel_launch(void* const* d_in, const int* in_sizes, int n_in,
                              void* d_out, int out_size) {
    const float* query = (const float*)d_in[0];
    const float* keys  = (const float*)d_in[1];
    const float* Wa_w  = (const float*)d_in[2];
    const float* Wa_b  = (const float*)d_in[3];
    const float* Ua_w  = (const float*)d_in[4];
    const float* Ua_b  = (const float*)d_in[5];
    const float* Va_w  = (const float*)d_in[6];
    // Va_b (d_in[7]) softmax-invariant; idx (d_in[8]) unused.

    float* out = (float*)d_out;
    float* ctx_out = out;             // (B,1,H)
    float* w_out   = out + B * H;     // (B,1,S)

    cudaFuncSetAttribute(k2_mma, cudaFuncAttributeMaxDynamicSharedMemorySize,
                         K2_SMEM);

    // K0: fp32 -> fp16 prepass (keys + Ua)
    k0_cvt<<<(KEY_GROUPS + UA_GROUPS) / 256, 256>>>(keys, Ua_w);

    k1_qproj<<<4096, 256>>>(query, Wa_w, Wa_b, Ua_b);

    dim3 g2(8, 512);
    k2_mma<<<g2, 256, K2_SMEM>>>(Va_w);

    k3_softmax<<<B, 256>>>(w_out);

    dim3 g4(B, H / 256, 4);
    k4_context<<<g4, 128>>>(w_out);
    k5_reduce<<<(B * H) / 256, 256>>>(ctx_out);
}